// round 10
// baseline (speedup 1.0000x reference)
#include <cuda_runtime.h>
#include <cuda_bf16.h>
#include <cstdint>
#include <cstddef>

// B=2, T=2048, H=2048, NUM_V=32, NUM_K=16, DK=DV=128, KCONV=4
// R8: resubmission of R6 kernel — R7 bench was a broker/container failure,
// no kernel signal. R6 fix (scalar stores into stride-65 Xs rows) still
// unvalidated; no other changes until a real measurement lands.
#define BT_TOT 4096
#define TT 2048
#define HID 2048
#define QKVZ_N 12288

// ---------------- scratch (__device__ globals; allocation is forbidden) -----
__device__ float g_qkvz[(size_t)BT_TOT * QKVZ_N];   // [bt][12288]
__device__ float g_ba  [(size_t)BT_TOT * 64];
__device__ float g_qn  [(size_t)BT_TOT * 2048];     // [bt][kh][128] (l2norm*scale)
__device__ float g_kn  [(size_t)BT_TOT * 2048];
__device__ float g_v   [(size_t)BT_TOT * 4096];     // [bt][vh][128]
__device__ float g_eg  [(size_t)BT_TOT * 32];       // exp(g)
__device__ float g_beta[(size_t)BT_TOT * 32];
__device__ float g_core[(size_t)BT_TOT * 4096];
__device__ float g_gated[(size_t)BT_TOT * 4096];

// ---------------- helpers ----------------
__device__ __forceinline__ uint32_t f2tf32(float f) {
    uint32_t r;
    asm("cvt.rna.tf32.f32 %0, %1;" : "=r"(r) : "f"(f));
    return r;
}

__device__ __forceinline__ void mma_tf32(float* d, const uint32_t* a, const uint32_t* b) {
    asm volatile(
        "mma.sync.aligned.m16n8k8.row.col.f32.tf32.tf32.f32 "
        "{%0,%1,%2,%3}, {%4,%5,%6,%7}, {%8,%9}, {%0,%1,%2,%3};\n"
        : "+f"(d[0]), "+f"(d[1]), "+f"(d[2]), "+f"(d[3])
        : "r"(a[0]), "r"(a[1]), "r"(a[2]), "r"(a[3]), "r"(b[0]), "r"(b[1]));
}

__device__ __forceinline__ float sigf(float x)  { return 1.f / (1.f + expf(-x)); }
__device__ __forceinline__ float siluf(float x) { return x / (1.f + expf(-x)); }

__device__ __forceinline__ float blockReduceSum128(float v) {
    #pragma unroll
    for (int off = 16; off > 0; off >>= 1)
        v += __shfl_xor_sync(0xffffffffu, v, off);
    __shared__ float red[4];
    int lane = threadIdx.x & 31, w = threadIdx.x >> 5;
    if (lane == 0) red[w] = v;
    __syncthreads();
    return red[0] + red[1] + red[2] + red[3];
}

// ---------------- split-tf32 tensor-core GEMM ----------------
// C[M,N] = A[M,K] * Bw[N,K]^T. Block tile 128x128, BK=32, 256 threads
// (8 warps, 4m x 2n, warp tile 32x64). 3xTF32 for ~fp32 accuracy.
__device__ __forceinline__ void gemm_body(const float* __restrict__ A,
                                          const float* __restrict__ Bw,
                                          float* __restrict__ C,
                                          int N, int K) {
    __shared__ float As[128 * 36];
    __shared__ float Bs[128 * 36];
    const int tid  = threadIdx.x;
    const int lane = tid & 31;
    const int wid  = tid >> 5;
    const int wm = (wid & 3) * 32;
    const int wn = (wid >> 2) * 64;
    const int g  = lane >> 2;
    const int tg = lane & 3;
    const int bm = blockIdx.y * 128;
    const int bn = blockIdx.x * 128;
    const int lr = tid >> 3;          // 0..31
    const int lc = (tid & 7) * 4;     // 0..28 (multiple of 4 -> 16B aligned in stride-36 rows)

    float acc[2][8][4];
    #pragma unroll
    for (int i = 0; i < 2; i++)
        #pragma unroll
        for (int j = 0; j < 8; j++)
            #pragma unroll
            for (int x = 0; x < 4; x++) acc[i][j][x] = 0.f;

    const float* Ag = A  + (size_t)(bm + lr) * K + lc;
    const float* Bg = Bw + (size_t)(bn + lr) * K + lc;

    for (int k0 = 0; k0 < K; k0 += 32) {
        #pragma unroll
        for (int i = 0; i < 4; i++) {
            *(float4*)&As[(lr + 32 * i) * 36 + lc] =
                *(const float4*)(Ag + (size_t)(32 * i) * K + k0);
            *(float4*)&Bs[(lr + 32 * i) * 36 + lc] =
                *(const float4*)(Bg + (size_t)(32 * i) * K + k0);
        }
        __syncthreads();
        #pragma unroll
        for (int ks = 0; ks < 32; ks += 8) {
            uint32_t ahi[2][4], alo[2][4];
            #pragma unroll
            for (int i = 0; i < 2; i++) {
                int r0 = (wm + i * 16 + g) * 36 + ks + tg;
                float fv[4];
                fv[0] = As[r0];
                fv[1] = As[r0 + 8 * 36];
                fv[2] = As[r0 + 4];
                fv[3] = As[r0 + 8 * 36 + 4];
                #pragma unroll
                for (int x = 0; x < 4; x++) {
                    ahi[i][x] = f2tf32(fv[x]);
                    alo[i][x] = f2tf32(fv[x] - __uint_as_float(ahi[i][x]));
                }
            }
            #pragma unroll
            for (int j = 0; j < 8; j++) {
                int c0 = (wn + j * 8 + g) * 36 + ks + tg;
                float bv0 = Bs[c0], bv1 = Bs[c0 + 4];
                uint32_t bhi[2], blo[2];
                bhi[0] = f2tf32(bv0); blo[0] = f2tf32(bv0 - __uint_as_float(bhi[0]));
                bhi[1] = f2tf32(bv1); blo[1] = f2tf32(bv1 - __uint_as_float(bhi[1]));
                #pragma unroll
                for (int i = 0; i < 2; i++) {
                    mma_tf32(acc[i][j], ahi[i], bhi);
                    mma_tf32(acc[i][j], ahi[i], blo);
                    mma_tf32(acc[i][j], alo[i], bhi);
                }
            }
        }
        __syncthreads();
    }
    #pragma unroll
    for (int i = 0; i < 2; i++) {
        int r0 = bm + wm + i * 16 + g;
        #pragma unroll
        for (int j = 0; j < 8; j++) {
            int c0 = bn + wn + j * 8 + tg * 2;
            *(float2*)&C[(size_t)r0 * N + c0]       = make_float2(acc[i][j][0], acc[i][j][1]);
            *(float2*)&C[(size_t)(r0 + 8) * N + c0] = make_float2(acc[i][j][2], acc[i][j][3]);
        }
    }
}

__global__ void __launch_bounds__(256, 2) gemm1_kernel(const float* __restrict__ A,
                                                       const float* __restrict__ Bw) {
    gemm_body(A, Bw, g_qkvz, QKVZ_N, HID);
}

__global__ void __launch_bounds__(256, 2) gemm2_kernel(const float* __restrict__ Bw,
                                                       float* __restrict__ C) {
    gemm_body(g_gated, Bw, C, HID, 4096);
}

// ---------------- ba = X @ W_ba^T (exact fp32; feeds exp recurrence) --------
__global__ void __launch_bounds__(256) ba_kernel(const float* __restrict__ X,
                                                 const float* __restrict__ Wba) {
    __shared__ float Xs[32 * 65];
    __shared__ float Ws[64 * 64];
    const int tid = threadIdx.x;
    const int btile = blockIdx.x * 32;
    const int m  = tid & 31;
    const int ng = tid >> 5;   // 0..7
    float acc[8];
    #pragma unroll
    for (int j = 0; j < 8; j++) acc[j] = 0.f;

    for (int k0 = 0; k0 < HID; k0 += 64) {
        {   // X tile 32x64: float4 global loads, SCALAR shared stores
            // (row stride 65 floats is not 16B-aligned for odd rows)
            int r = tid >> 3, cc = (tid & 7) * 8;
            float4 a = *(const float4*)(X + (size_t)(btile + r) * HID + k0 + cc);
            float4 bq = *(const float4*)(X + (size_t)(btile + r) * HID + k0 + cc + 4);
            float* row = &Xs[r * 65 + cc];
            row[0] = a.x;  row[1] = a.y;  row[2] = a.z;  row[3] = a.w;
            row[4] = bq.x; row[5] = bq.y; row[6] = bq.z; row[7] = bq.w;
        }
        {   // W tile 64x64 (stride 64 -> float4 aligned)
            int r = tid >> 2, cc = (tid & 3) * 16;
            #pragma unroll
            for (int u = 0; u < 4; u++)
                *(float4*)&Ws[r * 64 + cc + 4 * u] =
                    *(const float4*)(Wba + (size_t)r * HID + k0 + cc + 4 * u);
        }
        __syncthreads();
        #pragma unroll 4
        for (int k = 0; k < 64; k++) {
            float x = Xs[m * 65 + k];
            #pragma unroll
            for (int j = 0; j < 8; j++)
                acc[j] += x * Ws[(ng * 8 + j) * 64 + k];
        }
        __syncthreads();
    }
    #pragma unroll
    for (int j = 0; j < 8; j++)
        g_ba[(size_t)(btile + m) * 64 + ng * 8 + j] = acc[j];
}

// ---------------- beta / exp(g) ----------------
__global__ void __launch_bounds__(256) gb_kernel(const float* __restrict__ dt_bias,
                                                 const float* __restrict__ A_log) {
    int idx = blockIdx.x * 256 + threadIdx.x;     // 0..131071 = bt*32 + vh
    int bt = idx >> 5;
    int vh = idx & 31;
    int kh = vh >> 1;
    int r  = vh & 1;
    float bv = g_ba[(size_t)bt * 64 + kh * 4 + r];
    float av = g_ba[(size_t)bt * 64 + kh * 4 + 2 + r];
    g_beta[idx] = sigf(bv);
    float x = av + dt_bias[vh];
    float sp = (x > 20.f) ? x : log1pf(expf(x));
    g_eg[idx] = expf(-expf(A_log[vh]) * sp);
}

// ---------------- causal 4-tap depthwise conv + silu + l2norm(q,k) ----------
// grid (4096, 64): slot 0-15 q heads, 16-31 k heads, 32-63 v heads; 128 thr
__global__ void __launch_bounds__(128) conv_kernel(const float* __restrict__ conv_w) {
    const int bt = blockIdx.x;
    const int b  = bt >> 11;
    const int t  = bt & 2047;
    const int slot = blockIdx.y;
    const int d = threadIdx.x;

    int c, col, typ, head;
    if (slot < 16)      { head = slot;      c = head * 128 + d;        col = head * 768 + d;       typ = 0; }
    else if (slot < 32) { head = slot - 16; c = 2048 + head * 128 + d; col = head * 768 + 128 + d; typ = 1; }
    else {
        head = slot - 32; int kh = head >> 1; int r = head & 1;
        c = 4096 + head * 128 + d; col = kh * 768 + 256 + r * 128 + d; typ = 2;
    }

    const float w0 = conv_w[c * 4 + 0];
    const float w1 = conv_w[c * 4 + 1];
    const float w2 = conv_w[c * 4 + 2];
    const float w3 = conv_w[c * 4 + 3];
    const float* base = g_qkvz + (size_t)(b * TT) * QKVZ_N + col;

    float a = base[(size_t)t * QKVZ_N] * w3;
    if (t >= 1) a += base[(size_t)(t - 1) * QKVZ_N] * w2;
    if (t >= 2) a += base[(size_t)(t - 2) * QKVZ_N] * w1;
    if (t >= 3) a += base[(size_t)(t - 3) * QKVZ_N] * w0;
    float xs = siluf(a);

    if (typ == 2) {
        g_v[((size_t)bt * 32 + head) * 128 + d] = xs;
        return;
    }
    float total = blockReduceSum128(xs * xs);
    float val = xs * rsqrtf(total + 1e-6f);
    if (typ == 0) val *= 0.08838834764831845f;   // 128^-0.5
    float* dst = (typ == 0) ? g_qn : g_kn;
    dst[((size_t)bt * 16 + head) * 128 + d] = val;
}

// ---------------- gated delta-rule recurrence ----------------
// One warp per (b, vh, 4-column group): 2048 warps. Lane owns S[lane*4..+3][cb..cb+3].
__global__ void __launch_bounds__(128) recur_kernel() {
    const int lane = threadIdx.x & 31;
    const int wid  = threadIdx.x >> 5;
    const int gw = blockIdx.x * 4 + wid;      // 0..2047
    const int cb = (gw & 31) * 4;             // state column base
    const int vh = (gw >> 5) & 31;
    const int b  = gw >> 10;
    const int kh = vh >> 1;

    float S[4][4];
    #pragma unroll
    for (int i = 0; i < 4; i++)
        #pragma unroll
        for (int c2 = 0; c2 < 4; c2++) S[i][c2] = 0.f;

    const int k0 = lane * 4;
    const float* kp = g_kn + ((size_t)b * TT * 16 + kh) * 128 + k0;
    const float* qp = g_qn + ((size_t)b * TT * 16 + kh) * 128 + k0;
    const float* vp = g_v  + ((size_t)b * TT * 32 + vh) * 128 + cb;
    const float* ep = g_eg   + (size_t)b * TT * 32 + vh;
    const float* bp = g_beta + (size_t)b * TT * 32 + vh;
    float* op = g_core + ((size_t)b * TT * 32 + vh) * 128 + cb;

    for (int t = 0; t < TT; t++) {
        float4 k4 = *(const float4*)kp; kp += 2048;
        float4 q4 = *(const float4*)qp; qp += 2048;
        float4 v4 = *(const float4*)vp; vp += 4096;
        float e   = *ep; ep += 32;
        float bta = *bp; bp += 32;
        float kk[4] = {k4.x, k4.y, k4.z, k4.w};
        float qq[4] = {q4.x, q4.y, q4.z, q4.w};

        // decay + partial kv
        float p[4];
        #pragma unroll
        for (int c2 = 0; c2 < 4; c2++) {
            float s = 0.f;
            #pragma unroll
            for (int i = 0; i < 4; i++) {
                S[i][c2] *= e;
                s += S[i][c2] * kk[i];
            }
            p[c2] = s;
        }
        #pragma unroll
        for (int off = 16; off > 0; off >>= 1)
            #pragma unroll
            for (int c2 = 0; c2 < 4; c2++)
                p[c2] += __shfl_xor_sync(0xffffffffu, p[c2], off);

        float vv[4] = {v4.x, v4.y, v4.z, v4.w};
        float dl[4];
        #pragma unroll
        for (int c2 = 0; c2 < 4; c2++) dl[c2] = (vv[c2] - p[c2]) * bta;

        // state update + partial o
        float o[4];
        #pragma unroll
        for (int c2 = 0; c2 < 4; c2++) {
            float s = 0.f;
            #pragma unroll
            for (int i = 0; i < 4; i++) {
                S[i][c2] += kk[i] * dl[c2];
                s += S[i][c2] * qq[i];
            }
            o[c2] = s;
        }
        #pragma unroll
        for (int off = 16; off > 0; off >>= 1)
            #pragma unroll
            for (int c2 = 0; c2 < 4; c2++)
                o[c2] += __shfl_xor_sync(0xffffffffu, o[c2], off);

        if (lane == 0)
            *(float4*)op = make_float4(o[0], o[1], o[2], o[3]);
        op += 4096;
    }
}

// ---------------- gated RMSNorm: core * rsqrt(mean(core^2)+eps) * w * silu(z)
__global__ void __launch_bounds__(128) gated_kernel(const float* __restrict__ norm_weight) {
    const int bt = blockIdx.x;
    const int vh = blockIdx.y;
    const int d  = threadIdx.x;
    const int kh = vh >> 1, r = vh & 1;
    float c = g_core[((size_t)bt * 32 + vh) * 128 + d];
    float var = blockReduceSum128(c * c) * (1.f / 128.f);
    float z = g_qkvz[(size_t)bt * QKVZ_N + kh * 768 + 512 + r * 128 + d];
    g_gated[(size_t)bt * 4096 + vh * 128 + d] =
        c * rsqrtf(var + 1e-6f) * norm_weight[d] * siluf(z);
}

// ---------------- launch ----------------
extern "C" void kernel_launch(void* const* d_in, const int* in_sizes, int n_in,
                              void* d_out, int out_size) {
    const float* X        = (const float*)d_in[0];   // [2,2048,2048]
    const float* W_qkvz   = (const float*)d_in[1];   // [12288,2048]
    const float* W_ba     = (const float*)d_in[2];   // [64,2048]
    const float* conv_w   = (const float*)d_in[3];   // [8192,4]
    const float* dt_bias  = (const float*)d_in[4];   // [32]
    const float* A_log    = (const float*)d_in[5];   // [32]
    const float* norm_w   = (const float*)d_in[6];   // [128]
    const float* W_out    = (const float*)d_in[7];   // [2048,4096]
    float* out = (float*)d_out;

    gemm1_kernel<<<dim3(QKVZ_N / 128, BT_TOT / 128), 256>>>(X, W_qkvz);
    ba_kernel<<<BT_TOT / 32, 256>>>(X, W_ba);
    gb_kernel<<<(BT_TOT * 32) / 256, 256>>>(dt_bias, A_log);
    conv_kernel<<<dim3(BT_TOT, 64), 128>>>(conv_w);
    recur_kernel<<<512, 128>>>();
    gated_kernel<<<dim3(BT_TOT, 32), 128>>>(norm_w);
    gemm2_kernel<<<dim3(HID / 128, BT_TOT / 128), 256>>>(W_out, out);
}

// round 11
// speedup vs baseline: 1.5505x; 1.5505x over previous
#include <cuda_runtime.h>
#include <cuda_bf16.h>
#include <cstdint>
#include <cstddef>

// B=2, T=2048, H=2048, NUM_V=32, NUM_K=16, DK=DV=128, KCONV=4
// R10: R8 passed (7455us, rel_err 5.2e-5). GEMMs switched from 3xTF32 split
// (fp32-exact) to single-pass TF32 with tf32 values pre-converted at smem
// store time: 3x fewer mma + no per-read CVT/FADD split math. Headroom to
// 1e-3 threshold is ~20x; predicted rel_err ~2-4e-4.
#define BT_TOT 4096
#define TT 2048
#define HID 2048
#define QKVZ_N 12288

// ---------------- scratch (__device__ globals; allocation is forbidden) -----
__device__ float g_qkvz[(size_t)BT_TOT * QKVZ_N];   // [bt][12288]
__device__ float g_ba  [(size_t)BT_TOT * 64];
__device__ float g_qn  [(size_t)BT_TOT * 2048];     // [bt][kh][128] (l2norm*scale)
__device__ float g_kn  [(size_t)BT_TOT * 2048];
__device__ float g_v   [(size_t)BT_TOT * 4096];     // [bt][vh][128]
__device__ float g_eg  [(size_t)BT_TOT * 32];       // exp(g)
__device__ float g_beta[(size_t)BT_TOT * 32];
__device__ float g_core[(size_t)BT_TOT * 4096];
__device__ float g_gated[(size_t)BT_TOT * 4096];

// ---------------- helpers ----------------
__device__ __forceinline__ uint32_t f2tf32(float f) {
    uint32_t r;
    asm("cvt.rna.tf32.f32 %0, %1;" : "=r"(r) : "f"(f));
    return r;
}

__device__ __forceinline__ void mma_tf32(float* d, const uint32_t* a, const uint32_t* b) {
    asm volatile(
        "mma.sync.aligned.m16n8k8.row.col.f32.tf32.tf32.f32 "
        "{%0,%1,%2,%3}, {%4,%5,%6,%7}, {%8,%9}, {%0,%1,%2,%3};\n"
        : "+f"(d[0]), "+f"(d[1]), "+f"(d[2]), "+f"(d[3])
        : "r"(a[0]), "r"(a[1]), "r"(a[2]), "r"(a[3]), "r"(b[0]), "r"(b[1]));
}

__device__ __forceinline__ float sigf(float x)  { return 1.f / (1.f + expf(-x)); }
__device__ __forceinline__ float siluf(float x) { return x / (1.f + expf(-x)); }

__device__ __forceinline__ float blockReduceSum128(float v) {
    #pragma unroll
    for (int off = 16; off > 0; off >>= 1)
        v += __shfl_xor_sync(0xffffffffu, v, off);
    __shared__ float red[4];
    int lane = threadIdx.x & 31, w = threadIdx.x >> 5;
    if (lane == 0) red[w] = v;
    __syncthreads();
    return red[0] + red[1] + red[2] + red[3];
}

// ---------------- single-pass TF32 tensor-core GEMM ----------------
// C[M,N] = A[M,K] * Bw[N,K]^T. Block tile 128x128, BK=32, 256 threads
// (8 warps, 4m x 2n, warp tile 32x64). tf32 values pre-converted at smem
// store time -> mainloop is pure LDS + MMA.
__device__ __forceinline__ void gemm_body(const float* __restrict__ A,
                                          const float* __restrict__ Bw,
                                          float* __restrict__ C,
                                          int N, int K) {
    __shared__ uint32_t As[128 * 36];
    __shared__ uint32_t Bs[128 * 36];
    const int tid  = threadIdx.x;
    const int lane = tid & 31;
    const int wid  = tid >> 5;
    const int wm = (wid & 3) * 32;
    const int wn = (wid >> 2) * 64;
    const int g  = lane >> 2;
    const int tg = lane & 3;
    const int bm = blockIdx.y * 128;
    const int bn = blockIdx.x * 128;
    const int lr = tid >> 3;          // 0..31
    const int lc = (tid & 7) * 4;     // 0..28 (multiple of 4 -> 16B-aligned uint4 in stride-36 rows)

    float acc[2][8][4];
    #pragma unroll
    for (int i = 0; i < 2; i++)
        #pragma unroll
        for (int j = 0; j < 8; j++)
            #pragma unroll
            for (int x = 0; x < 4; x++) acc[i][j][x] = 0.f;

    const float* Ag = A  + (size_t)(bm + lr) * K + lc;
    const float* Bg = Bw + (size_t)(bn + lr) * K + lc;

    for (int k0 = 0; k0 < K; k0 += 32) {
        #pragma unroll
        for (int i = 0; i < 4; i++) {
            float4 va = *(const float4*)(Ag + (size_t)(32 * i) * K + k0);
            float4 vb = *(const float4*)(Bg + (size_t)(32 * i) * K + k0);
            uint4 ua = make_uint4(f2tf32(va.x), f2tf32(va.y), f2tf32(va.z), f2tf32(va.w));
            uint4 ub = make_uint4(f2tf32(vb.x), f2tf32(vb.y), f2tf32(vb.z), f2tf32(vb.w));
            *(uint4*)&As[(lr + 32 * i) * 36 + lc] = ua;
            *(uint4*)&Bs[(lr + 32 * i) * 36 + lc] = ub;
        }
        __syncthreads();
        #pragma unroll
        for (int ks = 0; ks < 32; ks += 8) {
            uint32_t af[2][4];
            #pragma unroll
            for (int i = 0; i < 2; i++) {
                int r0 = (wm + i * 16 + g) * 36 + ks + tg;
                af[i][0] = As[r0];
                af[i][1] = As[r0 + 8 * 36];
                af[i][2] = As[r0 + 4];
                af[i][3] = As[r0 + 8 * 36 + 4];
            }
            #pragma unroll
            for (int j = 0; j < 8; j++) {
                int c0 = (wn + j * 8 + g) * 36 + ks + tg;
                uint32_t bf[2];
                bf[0] = Bs[c0];
                bf[1] = Bs[c0 + 4];
                #pragma unroll
                for (int i = 0; i < 2; i++)
                    mma_tf32(acc[i][j], af[i], bf);
            }
        }
        __syncthreads();
    }
    #pragma unroll
    for (int i = 0; i < 2; i++) {
        int r0 = bm + wm + i * 16 + g;
        #pragma unroll
        for (int j = 0; j < 8; j++) {
            int c0 = bn + wn + j * 8 + tg * 2;
            *(float2*)&C[(size_t)r0 * N + c0]       = make_float2(acc[i][j][0], acc[i][j][1]);
            *(float2*)&C[(size_t)(r0 + 8) * N + c0] = make_float2(acc[i][j][2], acc[i][j][3]);
        }
    }
}

__global__ void __launch_bounds__(256, 2) gemm1_kernel(const float* __restrict__ A,
                                                       const float* __restrict__ Bw) {
    gemm_body(A, Bw, g_qkvz, QKVZ_N, HID);
}

__global__ void __launch_bounds__(256, 2) gemm2_kernel(const float* __restrict__ Bw,
                                                       float* __restrict__ C) {
    gemm_body(g_gated, Bw, C, HID, 4096);
}

// ---------------- ba = X @ W_ba^T (exact fp32; feeds exp recurrence) --------
__global__ void __launch_bounds__(256) ba_kernel(const float* __restrict__ X,
                                                 const float* __restrict__ Wba) {
    __shared__ float Xs[32 * 65];
    __shared__ float Ws[64 * 64];
    const int tid = threadIdx.x;
    const int btile = blockIdx.x * 32;
    const int m  = tid & 31;
    const int ng = tid >> 5;   // 0..7
    float acc[8];
    #pragma unroll
    for (int j = 0; j < 8; j++) acc[j] = 0.f;

    for (int k0 = 0; k0 < HID; k0 += 64) {
        {   // X tile 32x64: float4 global loads, SCALAR shared stores
            // (row stride 65 floats is not 16B-aligned for odd rows)
            int r = tid >> 3, cc = (tid & 7) * 8;
            float4 a = *(const float4*)(X + (size_t)(btile + r) * HID + k0 + cc);
            float4 bq = *(const float4*)(X + (size_t)(btile + r) * HID + k0 + cc + 4);
            float* row = &Xs[r * 65 + cc];
            row[0] = a.x;  row[1] = a.y;  row[2] = a.z;  row[3] = a.w;
            row[4] = bq.x; row[5] = bq.y; row[6] = bq.z; row[7] = bq.w;
        }
        {   // W tile 64x64 (stride 64 -> float4 aligned)
            int r = tid >> 2, cc = (tid & 3) * 16;
            #pragma unroll
            for (int u = 0; u < 4; u++)
                *(float4*)&Ws[r * 64 + cc + 4 * u] =
                    *(const float4*)(Wba + (size_t)r * HID + k0 + cc + 4 * u);
        }
        __syncthreads();
        #pragma unroll 4
        for (int k = 0; k < 64; k++) {
            float x = Xs[m * 65 + k];
            #pragma unroll
            for (int j = 0; j < 8; j++)
                acc[j] += x * Ws[(ng * 8 + j) * 64 + k];
        }
        __syncthreads();
    }
    #pragma unroll
    for (int j = 0; j < 8; j++)
        g_ba[(size_t)(btile + m) * 64 + ng * 8 + j] = acc[j];
}

// ---------------- beta / exp(g) ----------------
__global__ void __launch_bounds__(256) gb_kernel(const float* __restrict__ dt_bias,
                                                 const float* __restrict__ A_log) {
    int idx = blockIdx.x * 256 + threadIdx.x;     // 0..131071 = bt*32 + vh
    int bt = idx >> 5;
    int vh = idx & 31;
    int kh = vh >> 1;
    int r  = vh & 1;
    float bv = g_ba[(size_t)bt * 64 + kh * 4 + r];
    float av = g_ba[(size_t)bt * 64 + kh * 4 + 2 + r];
    g_beta[idx] = sigf(bv);
    float x = av + dt_bias[vh];
    float sp = (x > 20.f) ? x : log1pf(expf(x));
    g_eg[idx] = expf(-expf(A_log[vh]) * sp);
}

// ---------------- causal 4-tap depthwise conv + silu + l2norm(q,k) ----------
// grid (4096, 64): slot 0-15 q heads, 16-31 k heads, 32-63 v heads; 128 thr
__global__ void __launch_bounds__(128) conv_kernel(const float* __restrict__ conv_w) {
    const int bt = blockIdx.x;
    const int b  = bt >> 11;
    const int t  = bt & 2047;
    const int slot = blockIdx.y;
    const int d = threadIdx.x;

    int c, col, typ, head;
    if (slot < 16)      { head = slot;      c = head * 128 + d;        col = head * 768 + d;       typ = 0; }
    else if (slot < 32) { head = slot - 16; c = 2048 + head * 128 + d; col = head * 768 + 128 + d; typ = 1; }
    else {
        head = slot - 32; int kh = head >> 1; int r = head & 1;
        c = 4096 + head * 128 + d; col = kh * 768 + 256 + r * 128 + d; typ = 2;
    }

    const float w0 = conv_w[c * 4 + 0];
    const float w1 = conv_w[c * 4 + 1];
    const float w2 = conv_w[c * 4 + 2];
    const float w3 = conv_w[c * 4 + 3];
    const float* base = g_qkvz + (size_t)(b * TT) * QKVZ_N + col;

    float a = base[(size_t)t * QKVZ_N] * w3;
    if (t >= 1) a += base[(size_t)(t - 1) * QKVZ_N] * w2;
    if (t >= 2) a += base[(size_t)(t - 2) * QKVZ_N] * w1;
    if (t >= 3) a += base[(size_t)(t - 3) * QKVZ_N] * w0;
    float xs = siluf(a);

    if (typ == 2) {
        g_v[((size_t)bt * 32 + head) * 128 + d] = xs;
        return;
    }
    float total = blockReduceSum128(xs * xs);
    float val = xs * rsqrtf(total + 1e-6f);
    if (typ == 0) val *= 0.08838834764831845f;   // 128^-0.5
    float* dst = (typ == 0) ? g_qn : g_kn;
    dst[((size_t)bt * 16 + head) * 128 + d] = val;
}

// ---------------- gated delta-rule recurrence ----------------
// One warp per (b, vh, 4-column group): 2048 warps. Lane owns S[lane*4..+3][cb..cb+3].
__global__ void __launch_bounds__(128) recur_kernel() {
    const int lane = threadIdx.x & 31;
    const int wid  = threadIdx.x >> 5;
    const int gw = blockIdx.x * 4 + wid;      // 0..2047
    const int cb = (gw & 31) * 4;             // state column base
    const int vh = (gw >> 5) & 31;
    const int b  = gw >> 10;
    const int kh = vh >> 1;

    float S[4][4];
    #pragma unroll
    for (int i = 0; i < 4; i++)
        #pragma unroll
        for (int c2 = 0; c2 < 4; c2++) S[i][c2] = 0.f;

    const int k0 = lane * 4;
    const float* kp = g_kn + ((size_t)b * TT * 16 + kh) * 128 + k0;
    const float* qp = g_qn + ((size_t)b * TT * 16 + kh) * 128 + k0;
    const float* vp = g_v  + ((size_t)b * TT * 32 + vh) * 128 + cb;
    const float* ep = g_eg   + (size_t)b * TT * 32 + vh;
    const float* bp = g_beta + (size_t)b * TT * 32 + vh;
    float* op = g_core + ((size_t)b * TT * 32 + vh) * 128 + cb;

    for (int t = 0; t < TT; t++) {
        float4 k4 = *(const float4*)kp; kp += 2048;
        float4 q4 = *(const float4*)qp; qp += 2048;
        float4 v4 = *(const float4*)vp; vp += 4096;
        float e   = *ep; ep += 32;
        float bta = *bp; bp += 32;
        float kk[4] = {k4.x, k4.y, k4.z, k4.w};
        float qq[4] = {q4.x, q4.y, q4.z, q4.w};

        // decay + partial kv
        float p[4];
        #pragma unroll
        for (int c2 = 0; c2 < 4; c2++) {
            float s = 0.f;
            #pragma unroll
            for (int i = 0; i < 4; i++) {
                S[i][c2] *= e;
                s += S[i][c2] * kk[i];
            }
            p[c2] = s;
        }
        #pragma unroll
        for (int off = 16; off > 0; off >>= 1)
            #pragma unroll
            for (int c2 = 0; c2 < 4; c2++)
                p[c2] += __shfl_xor_sync(0xffffffffu, p[c2], off);

        float vv[4] = {v4.x, v4.y, v4.z, v4.w};
        float dl[4];
        #pragma unroll
        for (int c2 = 0; c2 < 4; c2++) dl[c2] = (vv[c2] - p[c2]) * bta;

        // state update + partial o
        float o[4];
        #pragma unroll
        for (int c2 = 0; c2 < 4; c2++) {
            float s = 0.f;
            #pragma unroll
            for (int i = 0; i < 4; i++) {
                S[i][c2] += kk[i] * dl[c2];
                s += S[i][c2] * qq[i];
            }
            o[c2] = s;
        }
        #pragma unroll
        for (int off = 16; off > 0; off >>= 1)
            #pragma unroll
            for (int c2 = 0; c2 < 4; c2++)
                o[c2] += __shfl_xor_sync(0xffffffffu, o[c2], off);

        if (lane == 0)
            *(float4*)op = make_float4(o[0], o[1], o[2], o[3]);
        op += 4096;
    }
}

// ---------------- gated RMSNorm: core * rsqrt(mean(core^2)+eps) * w * silu(z)
__global__ void __launch_bounds__(128) gated_kernel(const float* __restrict__ norm_weight) {
    const int bt = blockIdx.x;
    const int vh = blockIdx.y;
    const int d  = threadIdx.x;
    const int kh = vh >> 1, r = vh & 1;
    float c = g_core[((size_t)bt * 32 + vh) * 128 + d];
    float var = blockReduceSum128(c * c) * (1.f / 128.f);
    float z = g_qkvz[(size_t)bt * QKVZ_N + kh * 768 + 512 + r * 128 + d];
    g_gated[(size_t)bt * 4096 + vh * 128 + d] =
        c * rsqrtf(var + 1e-6f) * norm_weight[d] * siluf(z);
}

// ---------------- launch ----------------
extern "C" void kernel_launch(void* const* d_in, const int* in_sizes, int n_in,
                              void* d_out, int out_size) {
    const float* X        = (const float*)d_in[0];   // [2,2048,2048]
    const float* W_qkvz   = (const float*)d_in[1];   // [12288,2048]
    const float* W_ba     = (const float*)d_in[2];   // [64,2048]
    const float* conv_w   = (const float*)d_in[3];   // [8192,4]
    const float* dt_bias  = (const float*)d_in[4];   // [32]
    const float* A_log    = (const float*)d_in[5];   // [32]
    const float* norm_w   = (const float*)d_in[6];   // [128]
    const float* W_out    = (const float*)d_in[7];   // [2048,4096]
    float* out = (float*)d_out;

    gemm1_kernel<<<dim3(QKVZ_N / 128, BT_TOT / 128), 256>>>(X, W_qkvz);
    ba_kernel<<<BT_TOT / 32, 256>>>(X, W_ba);
    gb_kernel<<<(BT_TOT * 32) / 256, 256>>>(dt_bias, A_log);
    conv_kernel<<<dim3(BT_TOT, 64), 128>>>(conv_w);
    recur_kernel<<<512, 128>>>();
    gated_kernel<<<dim3(BT_TOT, 32), 128>>>(norm_w);
    gemm2_kernel<<<dim3(HID / 128, BT_TOT / 128), 256>>>(W_out, out);
}

// round 13
// speedup vs baseline: 2.1013x; 1.3552x over previous
#include <cuda_runtime.h>
#include <cuda_bf16.h>
#include <cstdint>
#include <cstddef>

// B=2, T=2048, H=2048, NUM_V=32, NUM_K=16, DK=DV=128, KCONV=4
// R13: redux.sync.add.f32 does NOT exist on sm_103 (ptxas error) -> revert
// warp reductions to SHFL butterfly (R11-identical math). KEEP the R12
// software prefetch in recur_kernel as the single measured delta vs R11
// (4808us, rel_err 6.8e-4).
#define BT_TOT 4096
#define TT 2048
#define HID 2048
#define QKVZ_N 12288

// ---------------- scratch (__device__ globals; allocation is forbidden) -----
__device__ float g_qkvz[(size_t)BT_TOT * QKVZ_N];   // [bt][12288]
__device__ float g_ba  [(size_t)BT_TOT * 64];
__device__ float g_qn  [(size_t)BT_TOT * 2048];     // [bt][kh][128] (l2norm*scale)
__device__ float g_kn  [(size_t)BT_TOT * 2048];
__device__ float g_v   [(size_t)BT_TOT * 4096];     // [bt][vh][128]
__device__ float g_eg  [(size_t)BT_TOT * 32];       // exp(g)
__device__ float g_beta[(size_t)BT_TOT * 32];
__device__ float g_core[(size_t)BT_TOT * 4096];
__device__ float g_gated[(size_t)BT_TOT * 4096];

// ---------------- helpers ----------------
__device__ __forceinline__ uint32_t f2tf32(float f) {
    uint32_t r;
    asm("cvt.rna.tf32.f32 %0, %1;" : "=r"(r) : "f"(f));
    return r;
}

__device__ __forceinline__ void mma_tf32(float* d, const uint32_t* a, const uint32_t* b) {
    asm volatile(
        "mma.sync.aligned.m16n8k8.row.col.f32.tf32.tf32.f32 "
        "{%0,%1,%2,%3}, {%4,%5,%6,%7}, {%8,%9}, {%0,%1,%2,%3};\n"
        : "+f"(d[0]), "+f"(d[1]), "+f"(d[2]), "+f"(d[3])
        : "r"(a[0]), "r"(a[1]), "r"(a[2]), "r"(a[3]), "r"(b[0]), "r"(b[1]));
}

__device__ __forceinline__ float sigf(float x)  { return 1.f / (1.f + expf(-x)); }
__device__ __forceinline__ float siluf(float x) { return x / (1.f + expf(-x)); }

__device__ __forceinline__ float warpSum(float v) {
    #pragma unroll
    for (int off = 16; off > 0; off >>= 1)
        v += __shfl_xor_sync(0xffffffffu, v, off);
    return v;
}

__device__ __forceinline__ float blockReduceSum128(float v) {
    v = warpSum(v);
    __shared__ float red[4];
    int lane = threadIdx.x & 31, w = threadIdx.x >> 5;
    if (lane == 0) red[w] = v;
    __syncthreads();
    return red[0] + red[1] + red[2] + red[3];
}

// ---------------- single-pass TF32 tensor-core GEMM ----------------
// C[M,N] = A[M,K] * Bw[N,K]^T. Block tile 128x128, BK=32, 256 threads
// (8 warps, 4m x 2n, warp tile 32x64). tf32 values pre-converted at smem
// store time -> mainloop is pure LDS + MMA.
__device__ __forceinline__ void gemm_body(const float* __restrict__ A,
                                          const float* __restrict__ Bw,
                                          float* __restrict__ C,
                                          int N, int K) {
    __shared__ uint32_t As[128 * 36];
    __shared__ uint32_t Bs[128 * 36];
    const int tid  = threadIdx.x;
    const int lane = tid & 31;
    const int wid  = tid >> 5;
    const int wm = (wid & 3) * 32;
    const int wn = (wid >> 2) * 64;
    const int g  = lane >> 2;
    const int tg = lane & 3;
    const int bm = blockIdx.y * 128;
    const int bn = blockIdx.x * 128;
    const int lr = tid >> 3;          // 0..31
    const int lc = (tid & 7) * 4;     // 0..28 (multiple of 4 -> 16B-aligned uint4 in stride-36 rows)

    float acc[2][8][4];
    #pragma unroll
    for (int i = 0; i < 2; i++)
        #pragma unroll
        for (int j = 0; j < 8; j++)
            #pragma unroll
            for (int x = 0; x < 4; x++) acc[i][j][x] = 0.f;

    const float* Ag = A  + (size_t)(bm + lr) * K + lc;
    const float* Bg = Bw + (size_t)(bn + lr) * K + lc;

    for (int k0 = 0; k0 < K; k0 += 32) {
        #pragma unroll
        for (int i = 0; i < 4; i++) {
            float4 va = *(const float4*)(Ag + (size_t)(32 * i) * K + k0);
            float4 vb = *(const float4*)(Bg + (size_t)(32 * i) * K + k0);
            uint4 ua = make_uint4(f2tf32(va.x), f2tf32(va.y), f2tf32(va.z), f2tf32(va.w));
            uint4 ub = make_uint4(f2tf32(vb.x), f2tf32(vb.y), f2tf32(vb.z), f2tf32(vb.w));
            *(uint4*)&As[(lr + 32 * i) * 36 + lc] = ua;
            *(uint4*)&Bs[(lr + 32 * i) * 36 + lc] = ub;
        }
        __syncthreads();
        #pragma unroll
        for (int ks = 0; ks < 32; ks += 8) {
            uint32_t af[2][4];
            #pragma unroll
            for (int i = 0; i < 2; i++) {
                int r0 = (wm + i * 16 + g) * 36 + ks + tg;
                af[i][0] = As[r0];
                af[i][1] = As[r0 + 8 * 36];
                af[i][2] = As[r0 + 4];
                af[i][3] = As[r0 + 8 * 36 + 4];
            }
            #pragma unroll
            for (int j = 0; j < 8; j++) {
                int c0 = (wn + j * 8 + g) * 36 + ks + tg;
                uint32_t bf[2];
                bf[0] = Bs[c0];
                bf[1] = Bs[c0 + 4];
                #pragma unroll
                for (int i = 0; i < 2; i++)
                    mma_tf32(acc[i][j], af[i], bf);
            }
        }
        __syncthreads();
    }
    #pragma unroll
    for (int i = 0; i < 2; i++) {
        int r0 = bm + wm + i * 16 + g;
        #pragma unroll
        for (int j = 0; j < 8; j++) {
            int c0 = bn + wn + j * 8 + tg * 2;
            *(float2*)&C[(size_t)r0 * N + c0]       = make_float2(acc[i][j][0], acc[i][j][1]);
            *(float2*)&C[(size_t)(r0 + 8) * N + c0] = make_float2(acc[i][j][2], acc[i][j][3]);
        }
    }
}

__global__ void __launch_bounds__(256, 2) gemm1_kernel(const float* __restrict__ A,
                                                       const float* __restrict__ Bw) {
    gemm_body(A, Bw, g_qkvz, QKVZ_N, HID);
}

__global__ void __launch_bounds__(256, 2) gemm2_kernel(const float* __restrict__ Bw,
                                                       float* __restrict__ C) {
    gemm_body(g_gated, Bw, C, HID, 4096);
}

// ---------------- ba = X @ W_ba^T (exact fp32; feeds exp recurrence) --------
__global__ void __launch_bounds__(256) ba_kernel(const float* __restrict__ X,
                                                 const float* __restrict__ Wba) {
    __shared__ float Xs[32 * 65];
    __shared__ float Ws[64 * 64];
    const int tid = threadIdx.x;
    const int btile = blockIdx.x * 32;
    const int m  = tid & 31;
    const int ng = tid >> 5;   // 0..7
    float acc[8];
    #pragma unroll
    for (int j = 0; j < 8; j++) acc[j] = 0.f;

    for (int k0 = 0; k0 < HID; k0 += 64) {
        {   // X tile 32x64: float4 global loads, SCALAR shared stores
            // (row stride 65 floats is not 16B-aligned for odd rows)
            int r = tid >> 3, cc = (tid & 7) * 8;
            float4 a = *(const float4*)(X + (size_t)(btile + r) * HID + k0 + cc);
            float4 bq = *(const float4*)(X + (size_t)(btile + r) * HID + k0 + cc + 4);
            float* row = &Xs[r * 65 + cc];
            row[0] = a.x;  row[1] = a.y;  row[2] = a.z;  row[3] = a.w;
            row[4] = bq.x; row[5] = bq.y; row[6] = bq.z; row[7] = bq.w;
        }
        {   // W tile 64x64 (stride 64 -> float4 aligned)
            int r = tid >> 2, cc = (tid & 3) * 16;
            #pragma unroll
            for (int u = 0; u < 4; u++)
                *(float4*)&Ws[r * 64 + cc + 4 * u] =
                    *(const float4*)(Wba + (size_t)r * HID + k0 + cc + 4 * u);
        }
        __syncthreads();
        #pragma unroll 4
        for (int k = 0; k < 64; k++) {
            float x = Xs[m * 65 + k];
            #pragma unroll
            for (int j = 0; j < 8; j++)
                acc[j] += x * Ws[(ng * 8 + j) * 64 + k];
        }
        __syncthreads();
    }
    #pragma unroll
    for (int j = 0; j < 8; j++)
        g_ba[(size_t)(btile + m) * 64 + ng * 8 + j] = acc[j];
}

// ---------------- beta / exp(g) ----------------
__global__ void __launch_bounds__(256) gb_kernel(const float* __restrict__ dt_bias,
                                                 const float* __restrict__ A_log) {
    int idx = blockIdx.x * 256 + threadIdx.x;     // 0..131071 = bt*32 + vh
    int bt = idx >> 5;
    int vh = idx & 31;
    int kh = vh >> 1;
    int r  = vh & 1;
    float bv = g_ba[(size_t)bt * 64 + kh * 4 + r];
    float av = g_ba[(size_t)bt * 64 + kh * 4 + 2 + r];
    g_beta[idx] = sigf(bv);
    float x = av + dt_bias[vh];
    float sp = (x > 20.f) ? x : log1pf(expf(x));
    g_eg[idx] = expf(-expf(A_log[vh]) * sp);
}

// ---------------- causal 4-tap depthwise conv + silu + l2norm(q,k) ----------
// grid (4096, 64): slot 0-15 q heads, 16-31 k heads, 32-63 v heads; 128 thr
__global__ void __launch_bounds__(128) conv_kernel(const float* __restrict__ conv_w) {
    const int bt = blockIdx.x;
    const int b  = bt >> 11;
    const int t  = bt & 2047;
    const int slot = blockIdx.y;
    const int d = threadIdx.x;

    int c, col, typ, head;
    if (slot < 16)      { head = slot;      c = head * 128 + d;        col = head * 768 + d;       typ = 0; }
    else if (slot < 32) { head = slot - 16; c = 2048 + head * 128 + d; col = head * 768 + 128 + d; typ = 1; }
    else {
        head = slot - 32; int kh = head >> 1; int r = head & 1;
        c = 4096 + head * 128 + d; col = kh * 768 + 256 + r * 128 + d; typ = 2;
    }

    const float w0 = conv_w[c * 4 + 0];
    const float w1 = conv_w[c * 4 + 1];
    const float w2 = conv_w[c * 4 + 2];
    const float w3 = conv_w[c * 4 + 3];
    const float* base = g_qkvz + (size_t)(b * TT) * QKVZ_N + col;

    float a = base[(size_t)t * QKVZ_N] * w3;
    if (t >= 1) a += base[(size_t)(t - 1) * QKVZ_N] * w2;
    if (t >= 2) a += base[(size_t)(t - 2) * QKVZ_N] * w1;
    if (t >= 3) a += base[(size_t)(t - 3) * QKVZ_N] * w0;
    float xs = siluf(a);

    if (typ == 2) {
        g_v[((size_t)bt * 32 + head) * 128 + d] = xs;
        return;
    }
    float total = blockReduceSum128(xs * xs);
    float val = xs * rsqrtf(total + 1e-6f);
    if (typ == 0) val *= 0.08838834764831845f;   // 128^-0.5
    float* dst = (typ == 0) ? g_qn : g_kn;
    dst[((size_t)bt * 16 + head) * 128 + d] = val;
}

// ---------------- gated delta-rule recurrence ----------------
// One warp per (b, vh, 4-column group): 2048 warps. Lane owns S[lane*4..+3][cb..cb+3].
// Software prefetch of next-step inputs keeps loads off the sequential
// critical path; reductions are SHFL butterflies (sm_103a has no redux.f32).
__global__ void __launch_bounds__(128) recur_kernel() {
    const int lane = threadIdx.x & 31;
    const int wid  = threadIdx.x >> 5;
    const int gw = blockIdx.x * 4 + wid;      // 0..2047
    const int cb = (gw & 31) * 4;             // state column base
    const int vh = (gw >> 5) & 31;
    const int b  = gw >> 10;
    const int kh = vh >> 1;

    float S[4][4];
    #pragma unroll
    for (int i = 0; i < 4; i++)
        #pragma unroll
        for (int c2 = 0; c2 < 4; c2++) S[i][c2] = 0.f;

    const int k0 = lane * 4;
    const float* kb = g_kn + ((size_t)b * TT * 16 + kh) * 128 + k0;
    const float* qb = g_qn + ((size_t)b * TT * 16 + kh) * 128 + k0;
    const float* vb = g_v  + ((size_t)b * TT * 32 + vh) * 128 + cb;
    const float* eb = g_eg   + (size_t)b * TT * 32 + vh;
    const float* bbp = g_beta + (size_t)b * TT * 32 + vh;
    float* op = g_core + ((size_t)b * TT * 32 + vh) * 128 + cb;

    // preload step 0
    float4 k4 = *(const float4*)kb;
    float4 q4 = *(const float4*)qb;
    float4 v4 = *(const float4*)vb;
    float e   = *eb;
    float bta = *bbp;

    for (int t = 0; t < TT; t++) {
        // prefetch step t+1 (clamped re-read of last step at the tail)
        int t2 = (t < TT - 1) ? t + 1 : t;
        float4 k4n = *(const float4*)(kb + (size_t)t2 * 2048);
        float4 q4n = *(const float4*)(qb + (size_t)t2 * 2048);
        float4 v4n = *(const float4*)(vb + (size_t)t2 * 4096);
        float  en  = eb[(size_t)t2 * 32];
        float  btn = bbp[(size_t)t2 * 32];

        float kk[4] = {k4.x, k4.y, k4.z, k4.w};
        float qq[4] = {q4.x, q4.y, q4.z, q4.w};

        // decay + partial kv
        float p[4];
        #pragma unroll
        for (int c2 = 0; c2 < 4; c2++) {
            float s = 0.f;
            #pragma unroll
            for (int i = 0; i < 4; i++) {
                S[i][c2] *= e;
                s += S[i][c2] * kk[i];
            }
            p[c2] = s;
        }
        #pragma unroll
        for (int off = 16; off > 0; off >>= 1)
            #pragma unroll
            for (int c2 = 0; c2 < 4; c2++)
                p[c2] += __shfl_xor_sync(0xffffffffu, p[c2], off);

        float vv[4] = {v4.x, v4.y, v4.z, v4.w};
        float dl[4];
        #pragma unroll
        for (int c2 = 0; c2 < 4; c2++) dl[c2] = (vv[c2] - p[c2]) * bta;

        // state update + partial o
        float o[4];
        #pragma unroll
        for (int c2 = 0; c2 < 4; c2++) {
            float s = 0.f;
            #pragma unroll
            for (int i = 0; i < 4; i++) {
                S[i][c2] += kk[i] * dl[c2];
                s += S[i][c2] * qq[i];
            }
            o[c2] = s;
        }
        #pragma unroll
        for (int off = 16; off > 0; off >>= 1)
            #pragma unroll
            for (int c2 = 0; c2 < 4; c2++)
                o[c2] += __shfl_xor_sync(0xffffffffu, o[c2], off);

        if (lane == 0)
            *(float4*)op = make_float4(o[0], o[1], o[2], o[3]);
        op += 4096;

        k4 = k4n; q4 = q4n; v4 = v4n; e = en; bta = btn;
    }
}

// ---------------- gated RMSNorm: core * rsqrt(mean(core^2)+eps) * w * silu(z)
__global__ void __launch_bounds__(128) gated_kernel(const float* __restrict__ norm_weight) {
    const int bt = blockIdx.x;
    const int vh = blockIdx.y;
    const int d  = threadIdx.x;
    const int kh = vh >> 1, r = vh & 1;
    float c = g_core[((size_t)bt * 32 + vh) * 128 + d];
    float var = blockReduceSum128(c * c) * (1.f / 128.f);
    float z = g_qkvz[(size_t)bt * QKVZ_N + kh * 768 + 512 + r * 128 + d];
    g_gated[(size_t)bt * 4096 + vh * 128 + d] =
        c * rsqrtf(var + 1e-6f) * norm_weight[d] * siluf(z);
}

// ---------------- launch ----------------
extern "C" void kernel_launch(void* const* d_in, const int* in_sizes, int n_in,
                              void* d_out, int out_size) {
    const float* X        = (const float*)d_in[0];   // [2,2048,2048]
    const float* W_qkvz   = (const float*)d_in[1];   // [12288,2048]
    const float* W_ba     = (const float*)d_in[2];   // [64,2048]
    const float* conv_w   = (const float*)d_in[3];   // [8192,4]
    const float* dt_bias  = (const float*)d_in[4];   // [32]
    const float* A_log    = (const float*)d_in[5];   // [32]
    const float* norm_w   = (const float*)d_in[6];   // [128]
    const float* W_out    = (const float*)d_in[7];   // [2048,4096]
    float* out = (float*)d_out;

    gemm1_kernel<<<dim3(QKVZ_N / 128, BT_TOT / 128), 256>>>(X, W_qkvz);
    ba_kernel<<<BT_TOT / 32, 256>>>(X, W_ba);
    gb_kernel<<<(BT_TOT * 32) / 256, 256>>>(dt_bias, A_log);
    conv_kernel<<<dim3(BT_TOT, 64), 128>>>(conv_w);
    recur_kernel<<<512, 128>>>();
    gated_kernel<<<dim3(BT_TOT, 32), 128>>>(norm_w);
    gemm2_kernel<<<dim3(HID / 128, BT_TOT / 128), 256>>>(W_out, out);
}

// round 14
// speedup vs baseline: 2.1141x; 1.0061x over previous
#include <cuda_runtime.h>
#include <cuda_bf16.h>
#include <cstdint>
#include <cstddef>

// B=2, T=2048, H=2048, NUM_V=32, NUM_K=16, DK=DV=128, KCONV=4
// R14: recur still latency-bound (~1.9ms est; only 3.46 warps/SMSP to hide a
// ~450cyc/step serial spine of SHFL trees + FFMA chains). Split state columns
// 4 -> 2 per warp: 4096 warps (6.9/SMSP), per-lane S[4][2], per-step issue
// ~110 inst. Same math order per column -> rel_err should stay 6.803e-4.
// GEMMs/conv/etc unchanged from R13 (3548us).
#define BT_TOT 4096
#define TT 2048
#define HID 2048
#define QKVZ_N 12288

// ---------------- scratch (__device__ globals; allocation is forbidden) -----
__device__ float g_qkvz[(size_t)BT_TOT * QKVZ_N];   // [bt][12288]
__device__ float g_ba  [(size_t)BT_TOT * 64];
__device__ float g_qn  [(size_t)BT_TOT * 2048];     // [bt][kh][128] (l2norm*scale)
__device__ float g_kn  [(size_t)BT_TOT * 2048];
__device__ float g_v   [(size_t)BT_TOT * 4096];     // [bt][vh][128]
__device__ float g_eg  [(size_t)BT_TOT * 32];       // exp(g)
__device__ float g_beta[(size_t)BT_TOT * 32];
__device__ float g_core[(size_t)BT_TOT * 4096];
__device__ float g_gated[(size_t)BT_TOT * 4096];

// ---------------- helpers ----------------
__device__ __forceinline__ uint32_t f2tf32(float f) {
    uint32_t r;
    asm("cvt.rna.tf32.f32 %0, %1;" : "=r"(r) : "f"(f));
    return r;
}

__device__ __forceinline__ void mma_tf32(float* d, const uint32_t* a, const uint32_t* b) {
    asm volatile(
        "mma.sync.aligned.m16n8k8.row.col.f32.tf32.tf32.f32 "
        "{%0,%1,%2,%3}, {%4,%5,%6,%7}, {%8,%9}, {%0,%1,%2,%3};\n"
        : "+f"(d[0]), "+f"(d[1]), "+f"(d[2]), "+f"(d[3])
        : "r"(a[0]), "r"(a[1]), "r"(a[2]), "r"(a[3]), "r"(b[0]), "r"(b[1]));
}

__device__ __forceinline__ float sigf(float x)  { return 1.f / (1.f + expf(-x)); }
__device__ __forceinline__ float siluf(float x) { return x / (1.f + expf(-x)); }

__device__ __forceinline__ float warpSum(float v) {
    #pragma unroll
    for (int off = 16; off > 0; off >>= 1)
        v += __shfl_xor_sync(0xffffffffu, v, off);
    return v;
}

__device__ __forceinline__ float blockReduceSum128(float v) {
    v = warpSum(v);
    __shared__ float red[4];
    int lane = threadIdx.x & 31, w = threadIdx.x >> 5;
    if (lane == 0) red[w] = v;
    __syncthreads();
    return red[0] + red[1] + red[2] + red[3];
}

// ---------------- single-pass TF32 tensor-core GEMM ----------------
// C[M,N] = A[M,K] * Bw[N,K]^T. Block tile 128x128, BK=32, 256 threads
// (8 warps, 4m x 2n, warp tile 32x64). tf32 values pre-converted at smem
// store time -> mainloop is pure LDS + MMA.
__device__ __forceinline__ void gemm_body(const float* __restrict__ A,
                                          const float* __restrict__ Bw,
                                          float* __restrict__ C,
                                          int N, int K) {
    __shared__ uint32_t As[128 * 36];
    __shared__ uint32_t Bs[128 * 36];
    const int tid  = threadIdx.x;
    const int lane = tid & 31;
    const int wid  = tid >> 5;
    const int wm = (wid & 3) * 32;
    const int wn = (wid >> 2) * 64;
    const int g  = lane >> 2;
    const int tg = lane & 3;
    const int bm = blockIdx.y * 128;
    const int bn = blockIdx.x * 128;
    const int lr = tid >> 3;          // 0..31
    const int lc = (tid & 7) * 4;     // 0..28 (multiple of 4 -> 16B-aligned uint4 in stride-36 rows)

    float acc[2][8][4];
    #pragma unroll
    for (int i = 0; i < 2; i++)
        #pragma unroll
        for (int j = 0; j < 8; j++)
            #pragma unroll
            for (int x = 0; x < 4; x++) acc[i][j][x] = 0.f;

    const float* Ag = A  + (size_t)(bm + lr) * K + lc;
    const float* Bg = Bw + (size_t)(bn + lr) * K + lc;

    for (int k0 = 0; k0 < K; k0 += 32) {
        #pragma unroll
        for (int i = 0; i < 4; i++) {
            float4 va = *(const float4*)(Ag + (size_t)(32 * i) * K + k0);
            float4 vb = *(const float4*)(Bg + (size_t)(32 * i) * K + k0);
            uint4 ua = make_uint4(f2tf32(va.x), f2tf32(va.y), f2tf32(va.z), f2tf32(va.w));
            uint4 ub = make_uint4(f2tf32(vb.x), f2tf32(vb.y), f2tf32(vb.z), f2tf32(vb.w));
            *(uint4*)&As[(lr + 32 * i) * 36 + lc] = ua;
            *(uint4*)&Bs[(lr + 32 * i) * 36 + lc] = ub;
        }
        __syncthreads();
        #pragma unroll
        for (int ks = 0; ks < 32; ks += 8) {
            uint32_t af[2][4];
            #pragma unroll
            for (int i = 0; i < 2; i++) {
                int r0 = (wm + i * 16 + g) * 36 + ks + tg;
                af[i][0] = As[r0];
                af[i][1] = As[r0 + 8 * 36];
                af[i][2] = As[r0 + 4];
                af[i][3] = As[r0 + 8 * 36 + 4];
            }
            #pragma unroll
            for (int j = 0; j < 8; j++) {
                int c0 = (wn + j * 8 + g) * 36 + ks + tg;
                uint32_t bf[2];
                bf[0] = Bs[c0];
                bf[1] = Bs[c0 + 4];
                #pragma unroll
                for (int i = 0; i < 2; i++)
                    mma_tf32(acc[i][j], af[i], bf);
            }
        }
        __syncthreads();
    }
    #pragma unroll
    for (int i = 0; i < 2; i++) {
        int r0 = bm + wm + i * 16 + g;
        #pragma unroll
        for (int j = 0; j < 8; j++) {
            int c0 = bn + wn + j * 8 + tg * 2;
            *(float2*)&C[(size_t)r0 * N + c0]       = make_float2(acc[i][j][0], acc[i][j][1]);
            *(float2*)&C[(size_t)(r0 + 8) * N + c0] = make_float2(acc[i][j][2], acc[i][j][3]);
        }
    }
}

__global__ void __launch_bounds__(256, 2) gemm1_kernel(const float* __restrict__ A,
                                                       const float* __restrict__ Bw) {
    gemm_body(A, Bw, g_qkvz, QKVZ_N, HID);
}

__global__ void __launch_bounds__(256, 2) gemm2_kernel(const float* __restrict__ Bw,
                                                       float* __restrict__ C) {
    gemm_body(g_gated, Bw, C, HID, 4096);
}

// ---------------- ba = X @ W_ba^T (exact fp32; feeds exp recurrence) --------
__global__ void __launch_bounds__(256) ba_kernel(const float* __restrict__ X,
                                                 const float* __restrict__ Wba) {
    __shared__ float Xs[32 * 65];
    __shared__ float Ws[64 * 64];
    const int tid = threadIdx.x;
    const int btile = blockIdx.x * 32;
    const int m  = tid & 31;
    const int ng = tid >> 5;   // 0..7
    float acc[8];
    #pragma unroll
    for (int j = 0; j < 8; j++) acc[j] = 0.f;

    for (int k0 = 0; k0 < HID; k0 += 64) {
        {   // X tile 32x64: float4 global loads, SCALAR shared stores
            // (row stride 65 floats is not 16B-aligned for odd rows)
            int r = tid >> 3, cc = (tid & 7) * 8;
            float4 a = *(const float4*)(X + (size_t)(btile + r) * HID + k0 + cc);
            float4 bq = *(const float4*)(X + (size_t)(btile + r) * HID + k0 + cc + 4);
            float* row = &Xs[r * 65 + cc];
            row[0] = a.x;  row[1] = a.y;  row[2] = a.z;  row[3] = a.w;
            row[4] = bq.x; row[5] = bq.y; row[6] = bq.z; row[7] = bq.w;
        }
        {   // W tile 64x64 (stride 64 -> float4 aligned)
            int r = tid >> 2, cc = (tid & 3) * 16;
            #pragma unroll
            for (int u = 0; u < 4; u++)
                *(float4*)&Ws[r * 64 + cc + 4 * u] =
                    *(const float4*)(Wba + (size_t)r * HID + k0 + cc + 4 * u);
        }
        __syncthreads();
        #pragma unroll 4
        for (int k = 0; k < 64; k++) {
            float x = Xs[m * 65 + k];
            #pragma unroll
            for (int j = 0; j < 8; j++)
                acc[j] += x * Ws[(ng * 8 + j) * 64 + k];
        }
        __syncthreads();
    }
    #pragma unroll
    for (int j = 0; j < 8; j++)
        g_ba[(size_t)(btile + m) * 64 + ng * 8 + j] = acc[j];
}

// ---------------- beta / exp(g) ----------------
__global__ void __launch_bounds__(256) gb_kernel(const float* __restrict__ dt_bias,
                                                 const float* __restrict__ A_log) {
    int idx = blockIdx.x * 256 + threadIdx.x;     // 0..131071 = bt*32 + vh
    int bt = idx >> 5;
    int vh = idx & 31;
    int kh = vh >> 1;
    int r  = vh & 1;
    float bv = g_ba[(size_t)bt * 64 + kh * 4 + r];
    float av = g_ba[(size_t)bt * 64 + kh * 4 + 2 + r];
    g_beta[idx] = sigf(bv);
    float x = av + dt_bias[vh];
    float sp = (x > 20.f) ? x : log1pf(expf(x));
    g_eg[idx] = expf(-expf(A_log[vh]) * sp);
}

// ---------------- causal 4-tap depthwise conv + silu + l2norm(q,k) ----------
// grid (4096, 64): slot 0-15 q heads, 16-31 k heads, 32-63 v heads; 128 thr
__global__ void __launch_bounds__(128) conv_kernel(const float* __restrict__ conv_w) {
    const int bt = blockIdx.x;
    const int b  = bt >> 11;
    const int t  = bt & 2047;
    const int slot = blockIdx.y;
    const int d = threadIdx.x;

    int c, col, typ, head;
    if (slot < 16)      { head = slot;      c = head * 128 + d;        col = head * 768 + d;       typ = 0; }
    else if (slot < 32) { head = slot - 16; c = 2048 + head * 128 + d; col = head * 768 + 128 + d; typ = 1; }
    else {
        head = slot - 32; int kh = head >> 1; int r = head & 1;
        c = 4096 + head * 128 + d; col = kh * 768 + 256 + r * 128 + d; typ = 2;
    }

    const float w0 = conv_w[c * 4 + 0];
    const float w1 = conv_w[c * 4 + 1];
    const float w2 = conv_w[c * 4 + 2];
    const float w3 = conv_w[c * 4 + 3];
    const float* base = g_qkvz + (size_t)(b * TT) * QKVZ_N + col;

    float a = base[(size_t)t * QKVZ_N] * w3;
    if (t >= 1) a += base[(size_t)(t - 1) * QKVZ_N] * w2;
    if (t >= 2) a += base[(size_t)(t - 2) * QKVZ_N] * w1;
    if (t >= 3) a += base[(size_t)(t - 3) * QKVZ_N] * w0;
    float xs = siluf(a);

    if (typ == 2) {
        g_v[((size_t)bt * 32 + head) * 128 + d] = xs;
        return;
    }
    float total = blockReduceSum128(xs * xs);
    float val = xs * rsqrtf(total + 1e-6f);
    if (typ == 0) val *= 0.08838834764831845f;   // 128^-0.5
    float* dst = (typ == 0) ? g_qn : g_kn;
    dst[((size_t)bt * 16 + head) * 128 + d] = val;
}

// ---------------- gated delta-rule recurrence ----------------
// One warp per (b, vh, 2-column group): 4096 warps. Lane owns S[lane*4..+3][cb..cb+1].
// Software prefetch keeps loads off the sequential critical path; 4 warps of a
// block share (b,vh) -> k/q rows dedup in L1.
__global__ void __launch_bounds__(128) recur_kernel() {
    const int lane = threadIdx.x & 31;
    const int wid  = threadIdx.x >> 5;
    const int gw = blockIdx.x * 4 + wid;      // 0..4095
    const int cb = (gw & 63) * 2;             // state column base (2 cols)
    const int vh = (gw >> 6) & 31;
    const int b  = gw >> 11;
    const int kh = vh >> 1;

    float S[4][2];
    #pragma unroll
    for (int i = 0; i < 4; i++)
        #pragma unroll
        for (int c2 = 0; c2 < 2; c2++) S[i][c2] = 0.f;

    const int k0 = lane * 4;
    const float* kb = g_kn + ((size_t)b * TT * 16 + kh) * 128 + k0;
    const float* qb = g_qn + ((size_t)b * TT * 16 + kh) * 128 + k0;
    const float* vb = g_v  + ((size_t)b * TT * 32 + vh) * 128 + cb;
    const float* eb = g_eg   + (size_t)b * TT * 32 + vh;
    const float* bbp = g_beta + (size_t)b * TT * 32 + vh;
    float* op = g_core + ((size_t)b * TT * 32 + vh) * 128 + cb;

    // preload step 0
    float4 k4 = *(const float4*)kb;
    float4 q4 = *(const float4*)qb;
    float2 v2 = *(const float2*)vb;
    float e   = *eb;
    float bta = *bbp;

    for (int t = 0; t < TT; t++) {
        // prefetch step t+1 (clamped re-read of last step at the tail)
        int t2 = (t < TT - 1) ? t + 1 : t;
        float4 k4n = *(const float4*)(kb + (size_t)t2 * 2048);
        float4 q4n = *(const float4*)(qb + (size_t)t2 * 2048);
        float2 v2n = *(const float2*)(vb + (size_t)t2 * 4096);
        float  en  = eb[(size_t)t2 * 32];
        float  btn = bbp[(size_t)t2 * 32];

        float kk[4] = {k4.x, k4.y, k4.z, k4.w};
        float qq[4] = {q4.x, q4.y, q4.z, q4.w};

        // decay + partial kv
        float p[2];
        #pragma unroll
        for (int c2 = 0; c2 < 2; c2++) {
            float s = 0.f;
            #pragma unroll
            for (int i = 0; i < 4; i++) {
                S[i][c2] *= e;
                s += S[i][c2] * kk[i];
            }
            p[c2] = s;
        }
        #pragma unroll
        for (int off = 16; off > 0; off >>= 1)
            #pragma unroll
            for (int c2 = 0; c2 < 2; c2++)
                p[c2] += __shfl_xor_sync(0xffffffffu, p[c2], off);

        float vv[2] = {v2.x, v2.y};
        float dl[2];
        #pragma unroll
        for (int c2 = 0; c2 < 2; c2++) dl[c2] = (vv[c2] - p[c2]) * bta;

        // state update + partial o
        float o[2];
        #pragma unroll
        for (int c2 = 0; c2 < 2; c2++) {
            float s = 0.f;
            #pragma unroll
            for (int i = 0; i < 4; i++) {
                S[i][c2] += kk[i] * dl[c2];
                s += S[i][c2] * qq[i];
            }
            o[c2] = s;
        }
        #pragma unroll
        for (int off = 16; off > 0; off >>= 1)
            #pragma unroll
            for (int c2 = 0; c2 < 2; c2++)
                o[c2] += __shfl_xor_sync(0xffffffffu, o[c2], off);

        if (lane == 0)
            *(float2*)op = make_float2(o[0], o[1]);
        op += 4096;

        k4 = k4n; q4 = q4n; v2 = v2n; e = en; bta = btn;
    }
}

// ---------------- gated RMSNorm: core * rsqrt(mean(core^2)+eps) * w * silu(z)
__global__ void __launch_bounds__(128) gated_kernel(const float* __restrict__ norm_weight) {
    const int bt = blockIdx.x;
    const int vh = blockIdx.y;
    const int d  = threadIdx.x;
    const int kh = vh >> 1, r = vh & 1;
    float c = g_core[((size_t)bt * 32 + vh) * 128 + d];
    float var = blockReduceSum128(c * c) * (1.f / 128.f);
    float z = g_qkvz[(size_t)bt * QKVZ_N + kh * 768 + 512 + r * 128 + d];
    g_gated[(size_t)bt * 4096 + vh * 128 + d] =
        c * rsqrtf(var + 1e-6f) * norm_weight[d] * siluf(z);
}

// ---------------- launch ----------------
extern "C" void kernel_launch(void* const* d_in, const int* in_sizes, int n_in,
                              void* d_out, int out_size) {
    const float* X        = (const float*)d_in[0];   // [2,2048,2048]
    const float* W_qkvz   = (const float*)d_in[1];   // [12288,2048]
    const float* W_ba     = (const float*)d_in[2];   // [64,2048]
    const float* conv_w   = (const float*)d_in[3];   // [8192,4]
    const float* dt_bias  = (const float*)d_in[4];   // [32]
    const float* A_log    = (const float*)d_in[5];   // [32]
    const float* norm_w   = (const float*)d_in[6];   // [128]
    const float* W_out    = (const float*)d_in[7];   // [2048,4096]
    float* out = (float*)d_out;

    gemm1_kernel<<<dim3(QKVZ_N / 128, BT_TOT / 128), 256>>>(X, W_qkvz);
    ba_kernel<<<BT_TOT / 32, 256>>>(X, W_ba);
    gb_kernel<<<(BT_TOT * 32) / 256, 256>>>(dt_bias, A_log);
    conv_kernel<<<dim3(BT_TOT, 64), 128>>>(conv_w);
    recur_kernel<<<1024, 128>>>();
    gated_kernel<<<dim3(BT_TOT, 32), 128>>>(norm_w);
    gemm2_kernel<<<dim3(HID / 128, BT_TOT / 128), 256>>>(W_out, out);
}

// round 15
// speedup vs baseline: 2.1350x; 1.0099x over previous
#include <cuda_runtime.h>
#include <cuda_bf16.h>
#include <cstdint>
#include <cstddef>

// B=2, T=2048, H=2048, NUM_V=32, NUM_K=16, DK=DV=128, KCONV=4
// R15: R14 (2x warps, same total SHFL) was NEUTRAL -> recur is SHFL-throughput
// bound. Restructure: 32 lanes = 8 k-groups x 4 columns; lane owns
// S[16 k][1 col]. Reductions span 8 lanes -> 3-level butterfly (xor 4,8,16),
// 6 SHFL/step vs 40. Warps back to 2048 (R13 layout), prefetch kept.
// GEMMs/conv/etc unchanged (R14: 3527us, rel_err 6.8e-4).
#define BT_TOT 4096
#define TT 2048
#define HID 2048
#define QKVZ_N 12288

// ---------------- scratch (__device__ globals; allocation is forbidden) -----
__device__ float g_qkvz[(size_t)BT_TOT * QKVZ_N];   // [bt][12288]
__device__ float g_ba  [(size_t)BT_TOT * 64];
__device__ float g_qn  [(size_t)BT_TOT * 2048];     // [bt][kh][128] (l2norm*scale)
__device__ float g_kn  [(size_t)BT_TOT * 2048];
__device__ float g_v   [(size_t)BT_TOT * 4096];     // [bt][vh][128]
__device__ float g_eg  [(size_t)BT_TOT * 32];       // exp(g)
__device__ float g_beta[(size_t)BT_TOT * 32];
__device__ float g_core[(size_t)BT_TOT * 4096];
__device__ float g_gated[(size_t)BT_TOT * 4096];

// ---------------- helpers ----------------
__device__ __forceinline__ uint32_t f2tf32(float f) {
    uint32_t r;
    asm("cvt.rna.tf32.f32 %0, %1;" : "=r"(r) : "f"(f));
    return r;
}

__device__ __forceinline__ void mma_tf32(float* d, const uint32_t* a, const uint32_t* b) {
    asm volatile(
        "mma.sync.aligned.m16n8k8.row.col.f32.tf32.tf32.f32 "
        "{%0,%1,%2,%3}, {%4,%5,%6,%7}, {%8,%9}, {%0,%1,%2,%3};\n"
        : "+f"(d[0]), "+f"(d[1]), "+f"(d[2]), "+f"(d[3])
        : "r"(a[0]), "r"(a[1]), "r"(a[2]), "r"(a[3]), "r"(b[0]), "r"(b[1]));
}

__device__ __forceinline__ float sigf(float x)  { return 1.f / (1.f + expf(-x)); }
__device__ __forceinline__ float siluf(float x) { return x / (1.f + expf(-x)); }

__device__ __forceinline__ float warpSum(float v) {
    #pragma unroll
    for (int off = 16; off > 0; off >>= 1)
        v += __shfl_xor_sync(0xffffffffu, v, off);
    return v;
}

__device__ __forceinline__ float blockReduceSum128(float v) {
    v = warpSum(v);
    __shared__ float red[4];
    int lane = threadIdx.x & 31, w = threadIdx.x >> 5;
    if (lane == 0) red[w] = v;
    __syncthreads();
    return red[0] + red[1] + red[2] + red[3];
}

// ---------------- single-pass TF32 tensor-core GEMM ----------------
// C[M,N] = A[M,K] * Bw[N,K]^T. Block tile 128x128, BK=32, 256 threads
// (8 warps, 4m x 2n, warp tile 32x64). tf32 values pre-converted at smem
// store time -> mainloop is pure LDS + MMA.
__device__ __forceinline__ void gemm_body(const float* __restrict__ A,
                                          const float* __restrict__ Bw,
                                          float* __restrict__ C,
                                          int N, int K) {
    __shared__ uint32_t As[128 * 36];
    __shared__ uint32_t Bs[128 * 36];
    const int tid  = threadIdx.x;
    const int lane = tid & 31;
    const int wid  = tid >> 5;
    const int wm = (wid & 3) * 32;
    const int wn = (wid >> 2) * 64;
    const int g  = lane >> 2;
    const int tg = lane & 3;
    const int bm = blockIdx.y * 128;
    const int bn = blockIdx.x * 128;
    const int lr = tid >> 3;          // 0..31
    const int lc = (tid & 7) * 4;     // 0..28 (multiple of 4 -> 16B-aligned uint4 in stride-36 rows)

    float acc[2][8][4];
    #pragma unroll
    for (int i = 0; i < 2; i++)
        #pragma unroll
        for (int j = 0; j < 8; j++)
            #pragma unroll
            for (int x = 0; x < 4; x++) acc[i][j][x] = 0.f;

    const float* Ag = A  + (size_t)(bm + lr) * K + lc;
    const float* Bg = Bw + (size_t)(bn + lr) * K + lc;

    for (int k0 = 0; k0 < K; k0 += 32) {
        #pragma unroll
        for (int i = 0; i < 4; i++) {
            float4 va = *(const float4*)(Ag + (size_t)(32 * i) * K + k0);
            float4 vb = *(const float4*)(Bg + (size_t)(32 * i) * K + k0);
            uint4 ua = make_uint4(f2tf32(va.x), f2tf32(va.y), f2tf32(va.z), f2tf32(va.w));
            uint4 ub = make_uint4(f2tf32(vb.x), f2tf32(vb.y), f2tf32(vb.z), f2tf32(vb.w));
            *(uint4*)&As[(lr + 32 * i) * 36 + lc] = ua;
            *(uint4*)&Bs[(lr + 32 * i) * 36 + lc] = ub;
        }
        __syncthreads();
        #pragma unroll
        for (int ks = 0; ks < 32; ks += 8) {
            uint32_t af[2][4];
            #pragma unroll
            for (int i = 0; i < 2; i++) {
                int r0 = (wm + i * 16 + g) * 36 + ks + tg;
                af[i][0] = As[r0];
                af[i][1] = As[r0 + 8 * 36];
                af[i][2] = As[r0 + 4];
                af[i][3] = As[r0 + 8 * 36 + 4];
            }
            #pragma unroll
            for (int j = 0; j < 8; j++) {
                int c0 = (wn + j * 8 + g) * 36 + ks + tg;
                uint32_t bf[2];
                bf[0] = Bs[c0];
                bf[1] = Bs[c0 + 4];
                #pragma unroll
                for (int i = 0; i < 2; i++)
                    mma_tf32(acc[i][j], af[i], bf);
            }
        }
        __syncthreads();
    }
    #pragma unroll
    for (int i = 0; i < 2; i++) {
        int r0 = bm + wm + i * 16 + g;
        #pragma unroll
        for (int j = 0; j < 8; j++) {
            int c0 = bn + wn + j * 8 + tg * 2;
            *(float2*)&C[(size_t)r0 * N + c0]       = make_float2(acc[i][j][0], acc[i][j][1]);
            *(float2*)&C[(size_t)(r0 + 8) * N + c0] = make_float2(acc[i][j][2], acc[i][j][3]);
        }
    }
}

__global__ void __launch_bounds__(256, 2) gemm1_kernel(const float* __restrict__ A,
                                                       const float* __restrict__ Bw) {
    gemm_body(A, Bw, g_qkvz, QKVZ_N, HID);
}

__global__ void __launch_bounds__(256, 2) gemm2_kernel(const float* __restrict__ Bw,
                                                       float* __restrict__ C) {
    gemm_body(g_gated, Bw, C, HID, 4096);
}

// ---------------- ba = X @ W_ba^T (exact fp32; feeds exp recurrence) --------
__global__ void __launch_bounds__(256) ba_kernel(const float* __restrict__ X,
                                                 const float* __restrict__ Wba) {
    __shared__ float Xs[32 * 65];
    __shared__ float Ws[64 * 64];
    const int tid = threadIdx.x;
    const int btile = blockIdx.x * 32;
    const int m  = tid & 31;
    const int ng = tid >> 5;   // 0..7
    float acc[8];
    #pragma unroll
    for (int j = 0; j < 8; j++) acc[j] = 0.f;

    for (int k0 = 0; k0 < HID; k0 += 64) {
        {   // X tile 32x64: float4 global loads, SCALAR shared stores
            // (row stride 65 floats is not 16B-aligned for odd rows)
            int r = tid >> 3, cc = (tid & 7) * 8;
            float4 a = *(const float4*)(X + (size_t)(btile + r) * HID + k0 + cc);
            float4 bq = *(const float4*)(X + (size_t)(btile + r) * HID + k0 + cc + 4);
            float* row = &Xs[r * 65 + cc];
            row[0] = a.x;  row[1] = a.y;  row[2] = a.z;  row[3] = a.w;
            row[4] = bq.x; row[5] = bq.y; row[6] = bq.z; row[7] = bq.w;
        }
        {   // W tile 64x64 (stride 64 -> float4 aligned)
            int r = tid >> 2, cc = (tid & 3) * 16;
            #pragma unroll
            for (int u = 0; u < 4; u++)
                *(float4*)&Ws[r * 64 + cc + 4 * u] =
                    *(const float4*)(Wba + (size_t)r * HID + k0 + cc + 4 * u);
        }
        __syncthreads();
        #pragma unroll 4
        for (int k = 0; k < 64; k++) {
            float x = Xs[m * 65 + k];
            #pragma unroll
            for (int j = 0; j < 8; j++)
                acc[j] += x * Ws[(ng * 8 + j) * 64 + k];
        }
        __syncthreads();
    }
    #pragma unroll
    for (int j = 0; j < 8; j++)
        g_ba[(size_t)(btile + m) * 64 + ng * 8 + j] = acc[j];
}

// ---------------- beta / exp(g) ----------------
__global__ void __launch_bounds__(256) gb_kernel(const float* __restrict__ dt_bias,
                                                 const float* __restrict__ A_log) {
    int idx = blockIdx.x * 256 + threadIdx.x;     // 0..131071 = bt*32 + vh
    int bt = idx >> 5;
    int vh = idx & 31;
    int kh = vh >> 1;
    int r  = vh & 1;
    float bv = g_ba[(size_t)bt * 64 + kh * 4 + r];
    float av = g_ba[(size_t)bt * 64 + kh * 4 + 2 + r];
    g_beta[idx] = sigf(bv);
    float x = av + dt_bias[vh];
    float sp = (x > 20.f) ? x : log1pf(expf(x));
    g_eg[idx] = expf(-expf(A_log[vh]) * sp);
}

// ---------------- causal 4-tap depthwise conv + silu + l2norm(q,k) ----------
// grid (4096, 64): slot 0-15 q heads, 16-31 k heads, 32-63 v heads; 128 thr
__global__ void __launch_bounds__(128) conv_kernel(const float* __restrict__ conv_w) {
    const int bt = blockIdx.x;
    const int b  = bt >> 11;
    const int t  = bt & 2047;
    const int slot = blockIdx.y;
    const int d = threadIdx.x;

    int c, col, typ, head;
    if (slot < 16)      { head = slot;      c = head * 128 + d;        col = head * 768 + d;       typ = 0; }
    else if (slot < 32) { head = slot - 16; c = 2048 + head * 128 + d; col = head * 768 + 128 + d; typ = 1; }
    else {
        head = slot - 32; int kh = head >> 1; int r = head & 1;
        c = 4096 + head * 128 + d; col = kh * 768 + 256 + r * 128 + d; typ = 2;
    }

    const float w0 = conv_w[c * 4 + 0];
    const float w1 = conv_w[c * 4 + 1];
    const float w2 = conv_w[c * 4 + 2];
    const float w3 = conv_w[c * 4 + 3];
    const float* base = g_qkvz + (size_t)(b * TT) * QKVZ_N + col;

    float a = base[(size_t)t * QKVZ_N] * w3;
    if (t >= 1) a += base[(size_t)(t - 1) * QKVZ_N] * w2;
    if (t >= 2) a += base[(size_t)(t - 2) * QKVZ_N] * w1;
    if (t >= 3) a += base[(size_t)(t - 3) * QKVZ_N] * w0;
    float xs = siluf(a);

    if (typ == 2) {
        g_v[((size_t)bt * 32 + head) * 128 + d] = xs;
        return;
    }
    float total = blockReduceSum128(xs * xs);
    float val = xs * rsqrtf(total + 1e-6f);
    if (typ == 0) val *= 0.08838834764831845f;   // 128^-0.5
    float* dst = (typ == 0) ? g_qn : g_kn;
    dst[((size_t)bt * 16 + head) * 128 + d] = val;
}

// ---------------- gated delta-rule recurrence ----------------
// One warp per (b, vh, 4-column group): 2048 warps. Lanes arranged as
// 8 k-groups x 4 columns: lane = kg*4 + cg owns S[16 k-entries][1 column].
// Reductions: 3-level butterfly over k-groups (xor 4,8,16) -> 6 SHFL/step.
// Software prefetch keeps loads off the sequential critical path.
__global__ void __launch_bounds__(128) recur_kernel() {
    const int lane = threadIdx.x & 31;
    const int wid  = threadIdx.x >> 5;
    const int gw = blockIdx.x * 4 + wid;      // 0..2047
    const int cb = (gw & 31) * 4;             // column base (4 cols per warp)
    const int vh = (gw >> 5) & 31;
    const int b  = gw >> 10;
    const int kh = vh >> 1;

    const int cg = lane & 3;                  // column group 0..3
    const int kg = lane >> 2;                 // k group 0..7
    const int col = cb + cg;                  // this lane's column
    const int k0 = kg * 16;                   // this lane's 16 k-entries

    float S[16];
    #pragma unroll
    for (int i = 0; i < 16; i++) S[i] = 0.f;

    const float* kb = g_kn + ((size_t)b * TT * 16 + kh) * 128 + k0;
    const float* qb = g_qn + ((size_t)b * TT * 16 + kh) * 128 + k0;
    const float* vb = g_v  + ((size_t)b * TT * 32 + vh) * 128 + col;
    const float* eb = g_eg   + (size_t)b * TT * 32 + vh;
    const float* bbp = g_beta + (size_t)b * TT * 32 + vh;
    float* op = g_core + ((size_t)b * TT * 32 + vh) * 128 + cb;

    // preload step 0
    float4 k4[4], q4[4];
    #pragma unroll
    for (int u = 0; u < 4; u++) {
        k4[u] = *(const float4*)(kb + 4 * u);
        q4[u] = *(const float4*)(qb + 4 * u);
    }
    float vv  = *vb;
    float e   = *eb;
    float bta = *bbp;

    for (int t = 0; t < TT; t++) {
        // prefetch step t+1 (clamped re-read of last step at the tail)
        int t2 = (t < TT - 1) ? t + 1 : t;
        float4 k4n[4], q4n[4];
        #pragma unroll
        for (int u = 0; u < 4; u++) {
            k4n[u] = *(const float4*)(kb + (size_t)t2 * 2048 + 4 * u);
            q4n[u] = *(const float4*)(qb + (size_t)t2 * 2048 + 4 * u);
        }
        float vn  = vb[(size_t)t2 * 4096];
        float en  = eb[(size_t)t2 * 32];
        float btn = bbp[(size_t)t2 * 32];

        const float* kk = (const float*)k4;
        const float* qq = (const float*)q4;

        // decay + partial kv (2 accumulators to shorten dep chain)
        float p0 = 0.f, p1 = 0.f;
        #pragma unroll
        for (int i = 0; i < 16; i += 2) {
            S[i]     *= e;
            S[i + 1] *= e;
            p0 += S[i]     * kk[i];
            p1 += S[i + 1] * kk[i + 1];
        }
        float p = p0 + p1;
        p += __shfl_xor_sync(0xffffffffu, p, 4);
        p += __shfl_xor_sync(0xffffffffu, p, 8);
        p += __shfl_xor_sync(0xffffffffu, p, 16);

        float dl = (vv - p) * bta;

        // state update + partial o
        float o0 = 0.f, o1 = 0.f;
        #pragma unroll
        for (int i = 0; i < 16; i += 2) {
            S[i]     += kk[i]     * dl;
            S[i + 1] += kk[i + 1] * dl;
            o0 += S[i]     * qq[i];
            o1 += S[i + 1] * qq[i + 1];
        }
        float o = o0 + o1;
        o += __shfl_xor_sync(0xffffffffu, o, 4);
        o += __shfl_xor_sync(0xffffffffu, o, 8);
        o += __shfl_xor_sync(0xffffffffu, o, 16);

        if (kg == 0)
            op[cg] = o;
        op += 4096;

        #pragma unroll
        for (int u = 0; u < 4; u++) { k4[u] = k4n[u]; q4[u] = q4n[u]; }
        vv = vn; e = en; bta = btn;
    }
}

// ---------------- gated RMSNorm: core * rsqrt(mean(core^2)+eps) * w * silu(z)
__global__ void __launch_bounds__(128) gated_kernel(const float* __restrict__ norm_weight) {
    const int bt = blockIdx.x;
    const int vh = blockIdx.y;
    const int d  = threadIdx.x;
    const int kh = vh >> 1, r = vh & 1;
    float c = g_core[((size_t)bt * 32 + vh) * 128 + d];
    float var = blockReduceSum128(c * c) * (1.f / 128.f);
    float z = g_qkvz[(size_t)bt * QKVZ_N + kh * 768 + 512 + r * 128 + d];
    g_gated[(size_t)bt * 4096 + vh * 128 + d] =
        c * rsqrtf(var + 1e-6f) * norm_weight[d] * siluf(z);
}

// ---------------- launch ----------------
extern "C" void kernel_launch(void* const* d_in, const int* in_sizes, int n_in,
                              void* d_out, int out_size) {
    const float* X        = (const float*)d_in[0];   // [2,2048,2048]
    const float* W_qkvz   = (const float*)d_in[1];   // [12288,2048]
    const float* W_ba     = (const float*)d_in[2];   // [64,2048]
    const float* conv_w   = (const float*)d_in[3];   // [8192,4]
    const float* dt_bias  = (const float*)d_in[4];   // [32]
    const float* A_log    = (const float*)d_in[5];   // [32]
    const float* norm_w   = (const float*)d_in[6];   // [128]
    const float* W_out    = (const float*)d_in[7];   // [2048,4096]
    float* out = (float*)d_out;

    gemm1_kernel<<<dim3(QKVZ_N / 128, BT_TOT / 128), 256>>>(X, W_qkvz);
    ba_kernel<<<BT_TOT / 32, 256>>>(X, W_ba);
    gb_kernel<<<(BT_TOT * 32) / 256, 256>>>(dt_bias, A_log);
    conv_kernel<<<dim3(BT_TOT, 64), 128>>>(conv_w);
    recur_kernel<<<512, 128>>>();
    gated_kernel<<<dim3(BT_TOT, 32), 128>>>(norm_w);
    gemm2_kernel<<<dim3(HID / 128, BT_TOT / 128), 256>>>(W_out, out);
}

// round 17
// speedup vs baseline: 2.1670x; 1.0149x over previous
#include <cuda_runtime.h>
#include <cuda_bf16.h>
#include <cstdint>
#include <cstddef>

// B=2, T=2048, H=2048, NUM_V=32, NUM_K=16, DK=DV=128, KCONV=4
// R17: resubmission of R16 — that bench died broker-side ("container failed
// twice", same as R5/R7), zero kernel signal. R16 deltas still unmeasured:
// (1) ba+gb fusion, (2) launch reorder so ncu slot profiles recur_kernel,
// (3) software-pipelined GEMM mainloop. recur unchanged from R15
// (3492us, rel_err 6.803e-4) so its profile is clean.
#define BT_TOT 4096
#define TT 2048
#define HID 2048
#define QKVZ_N 12288

// ---------------- scratch (__device__ globals; allocation is forbidden) -----
__device__ float g_qkvz[(size_t)BT_TOT * QKVZ_N];   // [bt][12288]
__device__ float g_qn  [(size_t)BT_TOT * 2048];     // [bt][kh][128] (l2norm*scale)
__device__ float g_kn  [(size_t)BT_TOT * 2048];
__device__ float g_v   [(size_t)BT_TOT * 4096];     // [bt][vh][128]
__device__ float g_eg  [(size_t)BT_TOT * 32];       // exp(g)
__device__ float g_beta[(size_t)BT_TOT * 32];
__device__ float g_core[(size_t)BT_TOT * 4096];
__device__ float g_gated[(size_t)BT_TOT * 4096];

// ---------------- helpers ----------------
__device__ __forceinline__ uint32_t f2tf32(float f) {
    uint32_t r;
    asm("cvt.rna.tf32.f32 %0, %1;" : "=r"(r) : "f"(f));
    return r;
}

__device__ __forceinline__ void mma_tf32(float* d, const uint32_t* a, const uint32_t* b) {
    asm volatile(
        "mma.sync.aligned.m16n8k8.row.col.f32.tf32.tf32.f32 "
        "{%0,%1,%2,%3}, {%4,%5,%6,%7}, {%8,%9}, {%0,%1,%2,%3};\n"
        : "+f"(d[0]), "+f"(d[1]), "+f"(d[2]), "+f"(d[3])
        : "r"(a[0]), "r"(a[1]), "r"(a[2]), "r"(a[3]), "r"(b[0]), "r"(b[1]));
}

__device__ __forceinline__ float sigf(float x)  { return 1.f / (1.f + expf(-x)); }
__device__ __forceinline__ float siluf(float x) { return x / (1.f + expf(-x)); }

__device__ __forceinline__ float warpSum(float v) {
    #pragma unroll
    for (int off = 16; off > 0; off >>= 1)
        v += __shfl_xor_sync(0xffffffffu, v, off);
    return v;
}

__device__ __forceinline__ float blockReduceSum128(float v) {
    v = warpSum(v);
    __shared__ float red[4];
    int lane = threadIdx.x & 31, w = threadIdx.x >> 5;
    if (lane == 0) red[w] = v;
    __syncthreads();
    return red[0] + red[1] + red[2] + red[3];
}

// ---------------- single-pass TF32 tensor-core GEMM (pipelined) -------------
// C[M,N] = A[M,K] * Bw[N,K]^T. Block tile 128x128, BK=32, 256 threads
// (8 warps, 4m x 2n, warp tile 32x64). Next k-tile is loaded into registers
// while the current tile computes; CVT+STS happen after the compute sync.
__device__ __forceinline__ void gemm_body(const float* __restrict__ A,
                                          const float* __restrict__ Bw,
                                          float* __restrict__ C,
                                          int N, int K) {
    __shared__ uint32_t As[128 * 36];
    __shared__ uint32_t Bs[128 * 36];
    const int tid  = threadIdx.x;
    const int lane = tid & 31;
    const int wid  = tid >> 5;
    const int wm = (wid & 3) * 32;
    const int wn = (wid >> 2) * 64;
    const int g  = lane >> 2;
    const int tg = lane & 3;
    const int bm = blockIdx.y * 128;
    const int bn = blockIdx.x * 128;
    const int lr = tid >> 3;          // 0..31
    const int lc = (tid & 7) * 4;     // 0..28 (multiple of 4 -> 16B-aligned uint4)

    float acc[2][8][4];
    #pragma unroll
    for (int i = 0; i < 2; i++)
        #pragma unroll
        for (int j = 0; j < 8; j++)
            #pragma unroll
            for (int x = 0; x < 4; x++) acc[i][j][x] = 0.f;

    const float* Ag = A  + (size_t)(bm + lr) * K + lc;
    const float* Bg = Bw + (size_t)(bn + lr) * K + lc;

    float4 pa[4], pb[4];
    // prologue: tile 0 -> regs -> smem
    #pragma unroll
    for (int i = 0; i < 4; i++) {
        pa[i] = *(const float4*)(Ag + (size_t)(32 * i) * K);
        pb[i] = *(const float4*)(Bg + (size_t)(32 * i) * K);
    }
    #pragma unroll
    for (int i = 0; i < 4; i++) {
        *(uint4*)&As[(lr + 32 * i) * 36 + lc] =
            make_uint4(f2tf32(pa[i].x), f2tf32(pa[i].y), f2tf32(pa[i].z), f2tf32(pa[i].w));
        *(uint4*)&Bs[(lr + 32 * i) * 36 + lc] =
            make_uint4(f2tf32(pb[i].x), f2tf32(pb[i].y), f2tf32(pb[i].z), f2tf32(pb[i].w));
    }
    __syncthreads();

    for (int k0 = 0; k0 < K; k0 += 32) {
        // issue loads for tile t+1 (consumed after compute)
        bool more = (k0 + 32) < K;
        if (more) {
            #pragma unroll
            for (int i = 0; i < 4; i++) {
                pa[i] = *(const float4*)(Ag + (size_t)(32 * i) * K + k0 + 32);
                pb[i] = *(const float4*)(Bg + (size_t)(32 * i) * K + k0 + 32);
            }
        }
        // compute current tile from smem
        #pragma unroll
        for (int ks = 0; ks < 32; ks += 8) {
            uint32_t af[2][4];
            #pragma unroll
            for (int i = 0; i < 2; i++) {
                int r0 = (wm + i * 16 + g) * 36 + ks + tg;
                af[i][0] = As[r0];
                af[i][1] = As[r0 + 8 * 36];
                af[i][2] = As[r0 + 4];
                af[i][3] = As[r0 + 8 * 36 + 4];
            }
            #pragma unroll
            for (int j = 0; j < 8; j++) {
                int c0 = (wn + j * 8 + g) * 36 + ks + tg;
                uint32_t bf[2];
                bf[0] = Bs[c0];
                bf[1] = Bs[c0 + 4];
                #pragma unroll
                for (int i = 0; i < 2; i++)
                    mma_tf32(acc[i][j], af[i], bf);
            }
        }
        __syncthreads();
        if (more) {
            #pragma unroll
            for (int i = 0; i < 4; i++) {
                *(uint4*)&As[(lr + 32 * i) * 36 + lc] =
                    make_uint4(f2tf32(pa[i].x), f2tf32(pa[i].y), f2tf32(pa[i].z), f2tf32(pa[i].w));
                *(uint4*)&Bs[(lr + 32 * i) * 36 + lc] =
                    make_uint4(f2tf32(pb[i].x), f2tf32(pb[i].y), f2tf32(pb[i].z), f2tf32(pb[i].w));
            }
            __syncthreads();
        }
    }
    #pragma unroll
    for (int i = 0; i < 2; i++) {
        int r0 = bm + wm + i * 16 + g;
        #pragma unroll
        for (int j = 0; j < 8; j++) {
            int c0 = bn + wn + j * 8 + tg * 2;
            *(float2*)&C[(size_t)r0 * N + c0]       = make_float2(acc[i][j][0], acc[i][j][1]);
            *(float2*)&C[(size_t)(r0 + 8) * N + c0] = make_float2(acc[i][j][2], acc[i][j][3]);
        }
    }
}

__global__ void __launch_bounds__(256, 2) gemm1_kernel(const float* __restrict__ A,
                                                       const float* __restrict__ Bw) {
    gemm_body(A, Bw, g_qkvz, QKVZ_N, HID);
}

__global__ void __launch_bounds__(256, 2) gemm2_kernel(const float* __restrict__ Bw,
                                                       float* __restrict__ C) {
    gemm_body(g_gated, Bw, C, HID, 4096);
}

// ---------------- ba = X @ W_ba^T, fused with beta/exp(g) ------------------
// Exact fp32 (feeds the exp recurrence). Thread (m, ng) holds outputs
// [ng*8, ng*8+8) = b/a pairs for key-heads 2ng, 2ng+1 = value-heads 4ng..4ng+3.
__global__ void __launch_bounds__(256) ba_kernel(const float* __restrict__ X,
                                                 const float* __restrict__ Wba,
                                                 const float* __restrict__ dt_bias,
                                                 const float* __restrict__ A_log) {
    __shared__ float Xs[32 * 65];
    __shared__ float Ws[64 * 64];
    const int tid = threadIdx.x;
    const int btile = blockIdx.x * 32;
    const int m  = tid & 31;
    const int ng = tid >> 5;   // 0..7
    float acc[8];
    #pragma unroll
    for (int j = 0; j < 8; j++) acc[j] = 0.f;

    for (int k0 = 0; k0 < HID; k0 += 64) {
        {   // X tile 32x64: float4 global loads, SCALAR shared stores
            // (row stride 65 floats is not 16B-aligned for odd rows)
            int r = tid >> 3, cc = (tid & 7) * 8;
            float4 a = *(const float4*)(X + (size_t)(btile + r) * HID + k0 + cc);
            float4 bq = *(const float4*)(X + (size_t)(btile + r) * HID + k0 + cc + 4);
            float* row = &Xs[r * 65 + cc];
            row[0] = a.x;  row[1] = a.y;  row[2] = a.z;  row[3] = a.w;
            row[4] = bq.x; row[5] = bq.y; row[6] = bq.z; row[7] = bq.w;
        }
        {   // W tile 64x64 (stride 64 -> float4 aligned)
            int r = tid >> 2, cc = (tid & 3) * 16;
            #pragma unroll
            for (int u = 0; u < 4; u++)
                *(float4*)&Ws[r * 64 + cc + 4 * u] =
                    *(const float4*)(Wba + (size_t)r * HID + k0 + cc + 4 * u);
        }
        __syncthreads();
        #pragma unroll 4
        for (int k = 0; k < 64; k++) {
            float x = Xs[m * 65 + k];
            #pragma unroll
            for (int j = 0; j < 8; j++)
                acc[j] += x * Ws[(ng * 8 + j) * 64 + k];
        }
        __syncthreads();
    }
    // fused gb: outputs for kh' in {0,1}: b_r = acc[kh'*4+r], a_r = acc[kh'*4+2+r]
    const int bt = btile + m;
    #pragma unroll
    for (int khp = 0; khp < 2; khp++) {
        #pragma unroll
        for (int r = 0; r < 2; r++) {
            int vh = (2 * ng + khp) * 2 + r;
            float bv = acc[khp * 4 + r];
            float av = acc[khp * 4 + 2 + r];
            g_beta[(size_t)bt * 32 + vh] = sigf(bv);
            float x = av + dt_bias[vh];
            float sp = (x > 20.f) ? x : log1pf(expf(x));
            g_eg[(size_t)bt * 32 + vh] = expf(-expf(A_log[vh]) * sp);
        }
    }
}

// ---------------- causal 4-tap depthwise conv + silu + l2norm(q,k) ----------
// grid (4096, 64): slot 0-15 q heads, 16-31 k heads, 32-63 v heads; 128 thr
__global__ void __launch_bounds__(128) conv_kernel(const float* __restrict__ conv_w) {
    const int bt = blockIdx.x;
    const int b  = bt >> 11;
    const int t  = bt & 2047;
    const int slot = blockIdx.y;
    const int d = threadIdx.x;

    int c, col, typ, head;
    if (slot < 16)      { head = slot;      c = head * 128 + d;        col = head * 768 + d;       typ = 0; }
    else if (slot < 32) { head = slot - 16; c = 2048 + head * 128 + d; col = head * 768 + 128 + d; typ = 1; }
    else {
        head = slot - 32; int kh = head >> 1; int r = head & 1;
        c = 4096 + head * 128 + d; col = kh * 768 + 256 + r * 128 + d; typ = 2;
    }

    const float w0 = conv_w[c * 4 + 0];
    const float w1 = conv_w[c * 4 + 1];
    const float w2 = conv_w[c * 4 + 2];
    const float w3 = conv_w[c * 4 + 3];
    const float* base = g_qkvz + (size_t)(b * TT) * QKVZ_N + col;

    float a = base[(size_t)t * QKVZ_N] * w3;
    if (t >= 1) a += base[(size_t)(t - 1) * QKVZ_N] * w2;
    if (t >= 2) a += base[(size_t)(t - 2) * QKVZ_N] * w1;
    if (t >= 3) a += base[(size_t)(t - 3) * QKVZ_N] * w0;
    float xs = siluf(a);

    if (typ == 2) {
        g_v[((size_t)bt * 32 + head) * 128 + d] = xs;
        return;
    }
    float total = blockReduceSum128(xs * xs);
    float val = xs * rsqrtf(total + 1e-6f);
    if (typ == 0) val *= 0.08838834764831845f;   // 128^-0.5
    float* dst = (typ == 0) ? g_qn : g_kn;
    dst[((size_t)bt * 16 + head) * 128 + d] = val;
}

// ---------------- gated delta-rule recurrence (unchanged from R15) ----------
// One warp per (b, vh, 4-column group): 2048 warps. Lanes arranged as
// 8 k-groups x 4 columns: lane = kg*4 + cg owns S[16 k-entries][1 column].
// Reductions: 3-level butterfly over k-groups; software prefetch distance 1.
__global__ void __launch_bounds__(128) recur_kernel() {
    const int lane = threadIdx.x & 31;
    const int wid  = threadIdx.x >> 5;
    const int gw = blockIdx.x * 4 + wid;      // 0..2047
    const int cb = (gw & 31) * 4;             // column base (4 cols per warp)
    const int vh = (gw >> 5) & 31;
    const int b  = gw >> 10;
    const int kh = vh >> 1;

    const int cg = lane & 3;                  // column group 0..3
    const int kg = lane >> 2;                 // k group 0..7
    const int col = cb + cg;                  // this lane's column
    const int k0 = kg * 16;                   // this lane's 16 k-entries

    float S[16];
    #pragma unroll
    for (int i = 0; i < 16; i++) S[i] = 0.f;

    const float* kb = g_kn + ((size_t)b * TT * 16 + kh) * 128 + k0;
    const float* qb = g_qn + ((size_t)b * TT * 16 + kh) * 128 + k0;
    const float* vb = g_v  + ((size_t)b * TT * 32 + vh) * 128 + col;
    const float* eb = g_eg   + (size_t)b * TT * 32 + vh;
    const float* bbp = g_beta + (size_t)b * TT * 32 + vh;
    float* op = g_core + ((size_t)b * TT * 32 + vh) * 128 + cb;

    // preload step 0
    float4 k4[4], q4[4];
    #pragma unroll
    for (int u = 0; u < 4; u++) {
        k4[u] = *(const float4*)(kb + 4 * u);
        q4[u] = *(const float4*)(qb + 4 * u);
    }
    float vv  = *vb;
    float e   = *eb;
    float bta = *bbp;

    for (int t = 0; t < TT; t++) {
        // prefetch step t+1 (clamped re-read of last step at the tail)
        int t2 = (t < TT - 1) ? t + 1 : t;
        float4 k4n[4], q4n[4];
        #pragma unroll
        for (int u = 0; u < 4; u++) {
            k4n[u] = *(const float4*)(kb + (size_t)t2 * 2048 + 4 * u);
            q4n[u] = *(const float4*)(qb + (size_t)t2 * 2048 + 4 * u);
        }
        float vn  = vb[(size_t)t2 * 4096];
        float en  = eb[(size_t)t2 * 32];
        float btn = bbp[(size_t)t2 * 32];

        const float* kk = (const float*)k4;
        const float* qq = (const float*)q4;

        // decay + partial kv (2 accumulators to shorten dep chain)
        float p0 = 0.f, p1 = 0.f;
        #pragma unroll
        for (int i = 0; i < 16; i += 2) {
            S[i]     *= e;
            S[i + 1] *= e;
            p0 += S[i]     * kk[i];
            p1 += S[i + 1] * kk[i + 1];
        }
        float p = p0 + p1;
        p += __shfl_xor_sync(0xffffffffu, p, 4);
        p += __shfl_xor_sync(0xffffffffu, p, 8);
        p += __shfl_xor_sync(0xffffffffu, p, 16);

        float dl = (vv - p) * bta;

        // state update + partial o
        float o0 = 0.f, o1 = 0.f;
        #pragma unroll
        for (int i = 0; i < 16; i += 2) {
            S[i]     += kk[i]     * dl;
            S[i + 1] += kk[i + 1] * dl;
            o0 += S[i]     * qq[i];
            o1 += S[i + 1] * qq[i + 1];
        }
        float o = o0 + o1;
        o += __shfl_xor_sync(0xffffffffu, o, 4);
        o += __shfl_xor_sync(0xffffffffu, o, 8);
        o += __shfl_xor_sync(0xffffffffu, o, 16);

        if (kg == 0)
            op[cg] = o;
        op += 4096;

        #pragma unroll
        for (int u = 0; u < 4; u++) { k4[u] = k4n[u]; q4[u] = q4n[u]; }
        vv = vn; e = en; bta = btn;
    }
}

// ---------------- gated RMSNorm: core * rsqrt(mean(core^2)+eps) * w * silu(z)
__global__ void __launch_bounds__(128) gated_kernel(const float* __restrict__ norm_weight) {
    const int bt = blockIdx.x;
    const int vh = blockIdx.y;
    const int d  = threadIdx.x;
    const int kh = vh >> 1, r = vh & 1;
    float c = g_core[((size_t)bt * 32 + vh) * 128 + d];
    float var = blockReduceSum128(c * c) * (1.f / 128.f);
    float z = g_qkvz[(size_t)bt * QKVZ_N + kh * 768 + 512 + r * 128 + d];
    g_gated[(size_t)bt * 4096 + vh * 128 + d] =
        c * rsqrtf(var + 1e-6f) * norm_weight[d] * siluf(z);
}

// ---------------- launch ----------------
// Order chosen so the ncu capture slot (process launch index 5 = our index 3)
// profiles recur_kernel: [ba, gemm1, conv, recur, gated, gemm2].
extern "C" void kernel_launch(void* const* d_in, const int* in_sizes, int n_in,
                              void* d_out, int out_size) {
    const float* X        = (const float*)d_in[0];   // [2,2048,2048]
    const float* W_qkvz   = (const float*)d_in[1];   // [12288,2048]
    const float* W_ba     = (const float*)d_in[2];   // [64,2048]
    const float* conv_w   = (const float*)d_in[3];   // [8192,4]
    const float* dt_bias  = (const float*)d_in[4];   // [32]
    const float* A_log    = (const float*)d_in[5];   // [32]
    const float* norm_w   = (const float*)d_in[6];   // [128]
    const float* W_out    = (const float*)d_in[7];   // [2048,4096]
    float* out = (float*)d_out;

    ba_kernel<<<BT_TOT / 32, 256>>>(X, W_ba, dt_bias, A_log);
    gemm1_kernel<<<dim3(QKVZ_N / 128, BT_TOT / 128), 256>>>(X, W_qkvz);
    conv_kernel<<<dim3(BT_TOT, 64), 128>>>(conv_w);
    recur_kernel<<<512, 128>>>();
    gated_kernel<<<dim3(BT_TOT, 32), 128>>>(norm_w);
    gemm2_kernel<<<dim3(HID / 128, BT_TOT / 128), 256>>>(W_out, out);
}